// round 5
// baseline (speedup 1.0000x reference)
#include <cuda_runtime.h>
#include <cuda_bf16.h>
#include <math.h>

#define NN 50000
#define EE 800000
#define F 128
#define BN_EPS 1e-5f
#define SCAN_B 1024
#define NBLK ((NN + SCAN_B - 1) / SCAN_B)

// ---------------- scratch ----------------
__device__ float g_agg[NN * 384];         // [n][k*128+o] aggregated features
__device__ float g_M[384 * 128];          // L @ W^T folded matrix
__device__ float g_proj[NN * 3];
__device__ float g_att[EE];
__device__ float g_inv[EE];
__device__ float g_m[NN];
__device__ float g_den[NN];
__device__ float g_sum[F];
__device__ float g_sum2[F];
__device__ int   g_cnt[NN];
__device__ int   g_scan[NN];
__device__ int   g_bsum[NBLK];
__device__ int   g_boff[NBLK];
__device__ int   g_off[NN + 1];
__device__ int   g_cur[NN];
__device__ long long g_pack[EE];          // {w (hi 32), src*4+order (lo 32)}

__device__ __forceinline__ void atomicMaxF(float* addr, float v) {
    if (v >= 0.f) atomicMax((int*)addr, __float_as_int(v));
    else          atomicMin((unsigned int*)addr, __float_as_uint(v));
}
// tf32 convert: b32 destination register (bit pattern)
__device__ __forceinline__ unsigned to_tf32(float x) {
    unsigned r;
    asm("cvt.rna.tf32.f32 %0, %1;" : "=r"(r) : "f"(x));
    return r;
}

// ---------------- kernels ----------------
__global__ void k_init(int n) {
    int i = blockIdx.x * blockDim.x + threadIdx.x;
    if (i < n) { g_m[i] = -INFINITY; g_den[i] = 0.f; g_cnt[i] = 0; }
    if (i < F) { g_sum[i] = 0.f; g_sum2[i] = 0.f; }
}

__global__ void k_proj(const float* __restrict__ feat,
                       const float* __restrict__ attW, int n) {
    int w = (blockIdx.x * blockDim.x + threadIdx.x) >> 5;
    int lane = threadIdx.x & 31;
    if (w >= n) return;
    float4 f = reinterpret_cast<const float4*>(feat + (size_t)w * F)[lane];
    const float4* aw = reinterpret_cast<const float4*>(attW);
    float4 w0 = aw[lane], w1 = aw[32 + lane], w2 = aw[64 + lane];
    float a0 = f.x * w0.x + f.y * w0.y + f.z * w0.z + f.w * w0.w;
    float a1 = f.x * w1.x + f.y * w1.y + f.z * w1.z + f.w * w1.w;
    float a2 = f.x * w2.x + f.y * w2.y + f.z * w2.z + f.w * w2.w;
#pragma unroll
    for (int off = 16; off; off >>= 1) {
        a0 += __shfl_down_sync(0xffffffffu, a0, off);
        a1 += __shfl_down_sync(0xffffffffu, a1, off);
        a2 += __shfl_down_sync(0xffffffffu, a2, off);
    }
    if (lane == 0) {
        g_proj[w * 3 + 0] = a0; g_proj[w * 3 + 1] = a1; g_proj[w * 3 + 2] = a2;
    }
}

__global__ void k_edgeA(const int* __restrict__ src, const int* __restrict__ dst,
                        const float* __restrict__ coords, int e) {
    int i = blockIdx.x * blockDim.x + threadIdx.x;
    if (i >= e) return;
    int s = src[i], d = dst[i];
    float dx = coords[s * 3 + 0] - coords[d * 3 + 0];
    float dy = coords[s * 3 + 1] - coords[d * 3 + 1];
    float dz = coords[s * 3 + 2] - coords[d * 3 + 2];
    float a = dx * g_proj[s * 3 + 0] + dy * g_proj[s * 3 + 1] + dz * g_proj[s * 3 + 2];
    g_att[i] = a;
    g_inv[i] = 1.f / (dx * dx + dy * dy + dz * dz + 1.f);
    atomicMaxF(&g_m[d], a);
    atomicAdd(&g_cnt[d], 1);
}

__global__ void k_scan_block(int n) {
    __shared__ int s[SCAN_B];
    int g = blockIdx.x * SCAN_B + threadIdx.x;
    int v = (g < n) ? g_cnt[g] : 0;
    s[threadIdx.x] = v;
    __syncthreads();
#pragma unroll
    for (int off = 1; off < SCAN_B; off <<= 1) {
        int t = (threadIdx.x >= off) ? s[threadIdx.x - off] : 0;
        __syncthreads();
        s[threadIdx.x] += t;
        __syncthreads();
    }
    if (g < n) g_scan[g] = s[threadIdx.x];
    if (threadIdx.x == SCAN_B - 1) g_bsum[blockIdx.x] = s[SCAN_B - 1];
}
__global__ void k_scan_top(int nb) {
    if (threadIdx.x == 0) {
        int acc = 0;
        for (int i = 0; i < nb; i++) { g_boff[i] = acc; acc += g_bsum[i]; }
    }
}
__global__ void k_scan_add(int n, int e) {
    int g = blockIdx.x * SCAN_B + threadIdx.x;
    if (g < n) {
        int excl = g_scan[g] - g_cnt[g] + g_boff[blockIdx.x];
        g_off[g] = excl;
        g_cur[g] = excl;
    }
    if (g == 0) g_off[n] = e;
}

__global__ void k_edgeB(const int* __restrict__ src, const int* __restrict__ dst,
                        const int* __restrict__ order, int e) {
    int i = blockIdx.x * blockDim.x + threadIdx.x;
    if (i >= e) return;
    int d = dst[i];
    float ex = expf(g_att[i] - g_m[d]);
    atomicAdd(&g_den[d], ex);
    float w = ex * g_inv[i];
    int idx = src[i] * 4 + order[i];
    int pos = atomicAdd(&g_cur[d], 1);
    g_pack[pos] = ((long long)__float_as_int(w) << 32) | (unsigned int)idx;
}

// aggregation: warp per dst; uniform linear reads of packed records (no shfl),
// unrolled so gathers overlap; 3 order-accumulators in registers, no atomics
__global__ void k_agg(const float* __restrict__ feat, int n) {
    int node = (blockIdx.x * blockDim.x + threadIdx.x) >> 5;
    int lane = threadIdx.x & 31;
    if (node >= n) return;
    int beg = g_off[node], end = g_off[node + 1];
    float den = g_den[node];
    float invden = 1.f / (den > 0.f ? den : 1.f);
    float4 a0 = make_float4(0.f, 0.f, 0.f, 0.f);
    float4 a1 = a0, a2 = a0;
    const float4* f4 = reinterpret_cast<const float4*>(feat);
#pragma unroll 4
    for (int j = beg; j < end; j++) {
        long long p = __ldg(&g_pack[j]);          // uniform → L1 broadcast
        int id = (int)(unsigned int)p;
        int s = id >> 2, k = id & 3;
        float w = __int_as_float((int)(p >> 32)) * invden;
        float4 v = f4[(size_t)s * 32 + lane];
        if (k == 0) {
            a0.x += w * v.x; a0.y += w * v.y; a0.z += w * v.z; a0.w += w * v.w;
        } else if (k == 1) {
            a1.x += w * v.x; a1.y += w * v.y; a1.z += w * v.z; a1.w += w * v.w;
        } else {
            a2.x += w * v.x; a2.y += w * v.y; a2.z += w * v.z; a2.w += w * v.w;
        }
    }
    float4* ap = reinterpret_cast<float4*>(g_agg + (size_t)node * 384);
    ap[lane] = a0;
    ap[32 + lane] = a1;
    ap[64 + lane] = a2;
}

// fold: M[r][o] = sum_j linear[r][j] * mlp_w[o][j]
__global__ void k_prep(const float* __restrict__ lin, const float* __restrict__ W) {
    extern __shared__ float smem[];
    float* swT = smem;              // [128][129]
    float* sL = smem + 128 * 129;   // [16][128]
    int t = threadIdx.x;
    int r0 = blockIdx.x * 16;
#pragma unroll 4
    for (int j = 0; j < F; j++)
        swT[t * 129 + j] = W[j * F + t];
    for (int idx = t; idx < 16 * F; idx += F)
        sL[idx] = lin[(size_t)r0 * F + idx];
    __syncthreads();
    float acc[16];
#pragma unroll
    for (int r = 0; r < 16; r++) acc[r] = 0.f;
#pragma unroll 4
    for (int j = 0; j < F; j++) {
        float wv = swT[j * 129 + t];
#pragma unroll
        for (int r = 0; r < 16; r++) acc[r] += sL[r * F + j] * wv;
    }
#pragma unroll
    for (int r = 0; r < 16; r++)
        g_M[(size_t)(r0 + r) * F + t] = acc[r];
}

// fused output GEMM (TF32 tensor cores): out = relu(Agg[N,384] @ M[384,128] + b)
// block: 128 rows x 128 cols, 8 warps; warp tile 32x64 (2 m-tiles x 8 n-tiles m16n8k8)
__global__ void __launch_bounds__(256, 1)
k_out_t(const float* __restrict__ mlp_b, float* __restrict__ out, int n) {
    __shared__ unsigned As[128][36];   // [m][k-chunk 32] tf32 bit patterns
    __shared__ unsigned Bs[32][132];   // [k][n]
    __shared__ float ssum[128], ssum2[128];
    int tid = threadIdx.x;
    int lane = tid & 31;
    int wid = tid >> 5;
    int wm = wid >> 1;              // 0..3 -> rows wm*32
    int wn = wid & 1;               // 0..1 -> cols wn*64
    int row0 = blockIdx.x * 128;

    if (tid < 128) { ssum[tid] = 0.f; ssum2[tid] = 0.f; }

    float c[2][8][4];
#pragma unroll
    for (int i = 0; i < 2; i++)
#pragma unroll
        for (int j = 0; j < 8; j++)
#pragma unroll
            for (int q = 0; q < 4; q++) c[i][j][q] = 0.f;

    for (int k0 = 0; k0 < 384; k0 += 32) {
        __syncthreads();
        // load A tile 128x32 (guard rows)
#pragma unroll
        for (int i = 0; i < 4; i++) {
            int lidx = i * 256 + tid;
            int row = lidx >> 3;
            int kq = (lidx & 7) * 4;
            float4 av = make_float4(0.f, 0.f, 0.f, 0.f);
            if (row0 + row < n)
                av = *reinterpret_cast<const float4*>(g_agg + (size_t)(row0 + row) * 384 + k0 + kq);
            As[row][kq + 0] = to_tf32(av.x);
            As[row][kq + 1] = to_tf32(av.y);
            As[row][kq + 2] = to_tf32(av.z);
            As[row][kq + 3] = to_tf32(av.w);
        }
        // load B tile 32x128
#pragma unroll
        for (int i = 0; i < 4; i++) {
            int lidx = i * 256 + tid;
            int krow = lidx >> 5;
            int nq = (lidx & 31) * 4;
            float4 bv = *reinterpret_cast<const float4*>(g_M + (size_t)(k0 + krow) * F + nq);
            Bs[krow][nq + 0] = to_tf32(bv.x);
            Bs[krow][nq + 1] = to_tf32(bv.y);
            Bs[krow][nq + 2] = to_tf32(bv.z);
            Bs[krow][nq + 3] = to_tf32(bv.w);
        }
        __syncthreads();

#pragma unroll
        for (int ks = 0; ks < 32; ks += 8) {
            // A fragments for 2 m-tiles
            unsigned a[2][4];
#pragma unroll
            for (int mt = 0; mt < 2; mt++) {
                int r = wm * 32 + mt * 16 + (lane >> 2);
                int kc = ks + (lane & 3);
                a[mt][0] = As[r][kc];
                a[mt][1] = As[r + 8][kc];
                a[mt][2] = As[r][kc + 4];
                a[mt][3] = As[r + 8][kc + 4];
            }
#pragma unroll
            for (int nt = 0; nt < 8; nt++) {
                int col = wn * 64 + nt * 8 + (lane >> 2);
                int kc = ks + (lane & 3);
                unsigned b0 = Bs[kc][col];
                unsigned b1 = Bs[kc + 4][col];
#pragma unroll
                for (int mt = 0; mt < 2; mt++) {
                    asm volatile(
                        "mma.sync.aligned.m16n8k8.row.col.f32.tf32.tf32.f32 "
                        "{%0,%1,%2,%3}, {%4,%5,%6,%7}, {%8,%9}, {%0,%1,%2,%3};"
                        : "+f"(c[mt][nt][0]), "+f"(c[mt][nt][1]),
                          "+f"(c[mt][nt][2]), "+f"(c[mt][nt][3])
                        : "r"(a[mt][0]), "r"(a[mt][1]), "r"(a[mt][2]), "r"(a[mt][3]),
                          "r"(b0), "r"(b1));
                }
            }
        }
    }
    __syncthreads();

    // epilogue: bias + relu + store + BN partial sums
#pragma unroll
    for (int mt = 0; mt < 2; mt++) {
#pragma unroll
        for (int nt = 0; nt < 8; nt++) {
            int colb = wn * 64 + nt * 8 + (lane & 3) * 2;
            int rowa = row0 + wm * 32 + mt * 16 + (lane >> 2);
            float b0 = mlp_b[colb], b1 = mlp_b[colb + 1];
#pragma unroll
            for (int h = 0; h < 2; h++) {
                int row = rowa + h * 8;
                if (row >= n) continue;
                float y0 = c[mt][nt][h * 2 + 0] + b0;
                float y1 = c[mt][nt][h * 2 + 1] + b1;
                y0 = y0 > 0.f ? y0 : 0.f;
                y1 = y1 > 0.f ? y1 : 0.f;
                out[(size_t)row * F + colb] = y0;
                out[(size_t)row * F + colb + 1] = y1;
                atomicAdd(&ssum[colb], y0);
                atomicAdd(&ssum[colb + 1], y1);
                atomicAdd(&ssum2[colb], y0 * y0);
                atomicAdd(&ssum2[colb + 1], y1 * y1);
            }
        }
    }
    __syncthreads();
    if (tid < 128) {
        atomicAdd(&g_sum[tid], ssum[tid]);
        atomicAdd(&g_sum2[tid], ssum2[tid]);
    }
}

__global__ void k_bn(float* __restrict__ out, const float* __restrict__ gamma,
                     const float* __restrict__ beta, int n) {
    int i = blockIdx.x * blockDim.x + threadIdx.x;
    if (i >= n * F) return;
    int o = i & (F - 1);
    float inv_n = 1.f / (float)n;
    float mean = g_sum[o] * inv_n;
    float var = g_sum2[o] * inv_n - mean * mean;
    float y = out[i];
    out[i] = (y - mean) * rsqrtf(var + BN_EPS) * gamma[o] + beta[o];
}

// ---------------- launch ----------------
extern "C" void kernel_launch(void* const* d_in, const int* in_sizes, int n_in,
                              void* d_out, int out_size) {
    const float* feature = (const float*)d_in[0];
    const float* coords  = (const float*)d_in[1];
    const int*   src     = (const int*)d_in[2];
    const int*   dst     = (const int*)d_in[3];
    const int*   order   = (const int*)d_in[4];
    const float* linear  = (const float*)d_in[5];
    const float* attW    = (const float*)d_in[6];
    const float* mlp_w   = (const float*)d_in[7];
    const float* mlp_b   = (const float*)d_in[8];
    const float* bn_gamma = (const float*)d_in[9];
    const float* bn_beta  = (const float*)d_in[10];
    float* out = (float*)d_out;

    int n = in_sizes[0] / F;
    int e = in_sizes[2];
    int nb = (n + SCAN_B - 1) / SCAN_B;

    k_init<<<(n + 255) / 256, 256>>>(n);
    k_proj<<<(n * 32 + 255) / 256, 256>>>(feature, attW, n);

    int smemp = (128 * 129 + 16 * F) * (int)sizeof(float);
    cudaFuncSetAttribute(k_prep, cudaFuncAttributeMaxDynamicSharedMemorySize, smemp);
    k_prep<<<384 / 16, 128, smemp>>>(linear, mlp_w);

    k_edgeA<<<(e + 255) / 256, 256>>>(src, dst, coords, e);
    k_scan_block<<<nb, SCAN_B>>>(n);
    k_scan_top<<<1, 32>>>(nb);
    k_scan_add<<<nb, SCAN_B>>>(n, e);
    k_edgeB<<<(e + 255) / 256, 256>>>(src, dst, order, e);
    k_agg<<<(n * 32 + 255) / 256, 256>>>(feature, n);

    k_out_t<<<(n + 127) / 128, 256>>>(mlp_b, out, n);
    k_bn<<<(n * F + 255) / 256, 256>>>(out, bn_gamma, bn_beta, n);
}

// round 6
// speedup vs baseline: 1.3562x; 1.3562x over previous
#include <cuda_runtime.h>
#include <cuda_bf16.h>
#include <math.h>

#define NN 50000
#define EE 800000
#define F 128
#define BN_EPS 1e-5f
#define SCAN_B 1024
#define NBLK ((NN + SCAN_B - 1) / SCAN_B)

// ---------------- scratch ----------------
__device__ float g_agg[NN * 384];         // [n][k*128+o] aggregated features
__device__ float g_M[384 * 128];          // L @ W^T folded matrix
__device__ float g_proj[NN * 3];
__device__ float g_att[EE];
__device__ float g_inv[EE];
__device__ float g_m[NN];
__device__ float g_den[NN];
__device__ float g_sum[F];
__device__ float g_sum2[F];
__device__ int   g_cnt[NN];
__device__ int   g_scan[NN];
__device__ int   g_bsum[NBLK];
__device__ int   g_boff[NBLK];
__device__ int   g_off[NN + 1];
__device__ int   g_cur[NN];
__device__ long long g_pack[EE];          // {w (hi 32), src*4+order (lo 32)}

__device__ __forceinline__ void atomicMaxF(float* addr, float v) {
    if (v >= 0.f) atomicMax((int*)addr, __float_as_int(v));
    else          atomicMin((unsigned int*)addr, __float_as_uint(v));
}
__device__ __forceinline__ unsigned to_tf32(float x) {
    unsigned r;
    asm("cvt.rna.tf32.f32 %0, %1;" : "=r"(r) : "f"(x));
    return r;
}

// ---------------- kernels ----------------
__global__ void k_init(int n) {
    int i = blockIdx.x * blockDim.x + threadIdx.x;
    if (i < n) { g_m[i] = -INFINITY; g_den[i] = 0.f; g_cnt[i] = 0; }
    if (i < F) { g_sum[i] = 0.f; g_sum2[i] = 0.f; }
}

__global__ void k_proj(const float* __restrict__ feat,
                       const float* __restrict__ attW, int n) {
    int w = (blockIdx.x * blockDim.x + threadIdx.x) >> 5;
    int lane = threadIdx.x & 31;
    if (w >= n) return;
    float4 f = reinterpret_cast<const float4*>(feat + (size_t)w * F)[lane];
    const float4* aw = reinterpret_cast<const float4*>(attW);
    float4 w0 = aw[lane], w1 = aw[32 + lane], w2 = aw[64 + lane];
    float a0 = f.x * w0.x + f.y * w0.y + f.z * w0.z + f.w * w0.w;
    float a1 = f.x * w1.x + f.y * w1.y + f.z * w1.z + f.w * w1.w;
    float a2 = f.x * w2.x + f.y * w2.y + f.z * w2.z + f.w * w2.w;
#pragma unroll
    for (int off = 16; off; off >>= 1) {
        a0 += __shfl_down_sync(0xffffffffu, a0, off);
        a1 += __shfl_down_sync(0xffffffffu, a1, off);
        a2 += __shfl_down_sync(0xffffffffu, a2, off);
    }
    if (lane == 0) {
        g_proj[w * 3 + 0] = a0; g_proj[w * 3 + 1] = a1; g_proj[w * 3 + 2] = a2;
    }
}

__global__ void k_edgeA(const int* __restrict__ src, const int* __restrict__ dst,
                        const float* __restrict__ coords, int e) {
    int i = blockIdx.x * blockDim.x + threadIdx.x;
    if (i >= e) return;
    int s = src[i], d = dst[i];
    float dx = coords[s * 3 + 0] - coords[d * 3 + 0];
    float dy = coords[s * 3 + 1] - coords[d * 3 + 1];
    float dz = coords[s * 3 + 2] - coords[d * 3 + 2];
    float a = dx * g_proj[s * 3 + 0] + dy * g_proj[s * 3 + 1] + dz * g_proj[s * 3 + 2];
    g_att[i] = a;
    g_inv[i] = 1.f / (dx * dx + dy * dy + dz * dz + 1.f);
    atomicMaxF(&g_m[d], a);
    atomicAdd(&g_cnt[d], 1);
}

__global__ void k_scan_block(int n) {
    __shared__ int s[SCAN_B];
    int g = blockIdx.x * SCAN_B + threadIdx.x;
    int v = (g < n) ? g_cnt[g] : 0;
    s[threadIdx.x] = v;
    __syncthreads();
#pragma unroll
    for (int off = 1; off < SCAN_B; off <<= 1) {
        int t = (threadIdx.x >= off) ? s[threadIdx.x - off] : 0;
        __syncthreads();
        s[threadIdx.x] += t;
        __syncthreads();
    }
    if (g < n) g_scan[g] = s[threadIdx.x];
    if (threadIdx.x == SCAN_B - 1) g_bsum[blockIdx.x] = s[SCAN_B - 1];
}
__global__ void k_scan_top(int nb) {
    if (threadIdx.x == 0) {
        int acc = 0;
        for (int i = 0; i < nb; i++) { g_boff[i] = acc; acc += g_bsum[i]; }
    }
}
__global__ void k_scan_add(int n, int e) {
    int g = blockIdx.x * SCAN_B + threadIdx.x;
    if (g < n) {
        int excl = g_scan[g] - g_cnt[g] + g_boff[blockIdx.x];
        g_off[g] = excl;
        g_cur[g] = excl;
    }
    if (g == 0) g_off[n] = e;
}

__global__ void k_edgeB(const int* __restrict__ src, const int* __restrict__ dst,
                        const int* __restrict__ order, int e) {
    int i = blockIdx.x * blockDim.x + threadIdx.x;
    if (i >= e) return;
    int d = dst[i];
    float ex = expf(g_att[i] - g_m[d]);
    atomicAdd(&g_den[d], ex);
    float w = ex * g_inv[i];
    int idx = src[i] * 4 + order[i];
    int pos = atomicAdd(&g_cur[d], 1);
    g_pack[pos] = ((long long)__float_as_int(w) << 32) | (unsigned int)idx;
}

// aggregation (R3 known-good): warp per dst, shfl-batched records, no atomics
__global__ void k_agg(const float* __restrict__ feat, int n) {
    int node = (blockIdx.x * blockDim.x + threadIdx.x) >> 5;
    int lane = threadIdx.x & 31;
    if (node >= n) return;
    int beg = g_off[node], end = g_off[node + 1];
    float den = g_den[node];
    float invden = 1.f / (den > 0.f ? den : 1.f);
    float4 a0 = make_float4(0.f, 0.f, 0.f, 0.f);
    float4 a1 = a0, a2 = a0;
    const float4* f4 = reinterpret_cast<const float4*>(feat);
    for (int base = beg; base < end; base += 32) {
        int idx = base + lane;
        long long pk = (idx < end) ? g_pack[idx] : 0;
        int cnt = min(32, end - base);
        for (int j = 0; j < cnt; j++) {
            long long p = __shfl_sync(0xffffffffu, pk, j);
            int id = (int)(unsigned int)p;
            int s = id >> 2, k = id & 3;
            float w = __int_as_float((int)(p >> 32)) * invden;
            float4 v = f4[(size_t)s * 32 + lane];
            if (k == 0) {
                a0.x += w * v.x; a0.y += w * v.y; a0.z += w * v.z; a0.w += w * v.w;
            } else if (k == 1) {
                a1.x += w * v.x; a1.y += w * v.y; a1.z += w * v.z; a1.w += w * v.w;
            } else {
                a2.x += w * v.x; a2.y += w * v.y; a2.z += w * v.z; a2.w += w * v.w;
            }
        }
    }
    float4* ap = reinterpret_cast<float4*>(g_agg + (size_t)node * 384);
    ap[lane] = a0;
    ap[32 + lane] = a1;
    ap[64 + lane] = a2;
}

// fold: M[r][o] = sum_j linear[r][j] * mlp_w[o][j]
__global__ void k_prep(const float* __restrict__ lin, const float* __restrict__ W) {
    extern __shared__ float smem[];
    float* swT = smem;              // [128][129]
    float* sL = smem + 128 * 129;   // [16][128]
    int t = threadIdx.x;
    int r0 = blockIdx.x * 16;
#pragma unroll 4
    for (int j = 0; j < F; j++)
        swT[t * 129 + j] = W[j * F + t];
    for (int idx = t; idx < 16 * F; idx += F)
        sL[idx] = lin[(size_t)r0 * F + idx];
    __syncthreads();
    float acc[16];
#pragma unroll
    for (int r = 0; r < 16; r++) acc[r] = 0.f;
#pragma unroll 4
    for (int j = 0; j < F; j++) {
        float wv = swT[j * 129 + t];
#pragma unroll
        for (int r = 0; r < 16; r++) acc[r] += sL[r * F + j] * wv;
    }
#pragma unroll
    for (int r = 0; r < 16; r++)
        g_M[(size_t)(r0 + r) * F + t] = acc[r];
}

// fused output GEMM (TF32 tensor cores): out = relu(Agg[N,384] @ M[384,128] + b)
// BN sums accumulated in registers over (mt,h), then 32 shared atomics/thread.
__global__ void __launch_bounds__(256, 1)
k_out_t(const float* __restrict__ mlp_b, float* __restrict__ out, int n) {
    __shared__ unsigned As[128][36];   // [m][k-chunk 32] tf32 bit patterns
    __shared__ unsigned Bs[32][132];   // [k][n]
    __shared__ float ssum[128], ssum2[128];
    int tid = threadIdx.x;
    int lane = tid & 31;
    int wid = tid >> 5;
    int wm = wid >> 1;              // 0..3 -> rows wm*32
    int wn = wid & 1;               // 0..1 -> cols wn*64
    int row0 = blockIdx.x * 128;

    if (tid < 128) { ssum[tid] = 0.f; ssum2[tid] = 0.f; }

    float c[2][8][4];
#pragma unroll
    for (int i = 0; i < 2; i++)
#pragma unroll
        for (int j = 0; j < 8; j++)
#pragma unroll
            for (int q = 0; q < 4; q++) c[i][j][q] = 0.f;

    for (int k0 = 0; k0 < 384; k0 += 32) {
        __syncthreads();
#pragma unroll
        for (int i = 0; i < 4; i++) {
            int lidx = i * 256 + tid;
            int row = lidx >> 3;
            int kq = (lidx & 7) * 4;
            float4 av = make_float4(0.f, 0.f, 0.f, 0.f);
            if (row0 + row < n)
                av = *reinterpret_cast<const float4*>(g_agg + (size_t)(row0 + row) * 384 + k0 + kq);
            As[row][kq + 0] = to_tf32(av.x);
            As[row][kq + 1] = to_tf32(av.y);
            As[row][kq + 2] = to_tf32(av.z);
            As[row][kq + 3] = to_tf32(av.w);
        }
#pragma unroll
        for (int i = 0; i < 4; i++) {
            int lidx = i * 256 + tid;
            int krow = lidx >> 5;
            int nq = (lidx & 31) * 4;
            float4 bv = *reinterpret_cast<const float4*>(g_M + (size_t)(k0 + krow) * F + nq);
            Bs[krow][nq + 0] = to_tf32(bv.x);
            Bs[krow][nq + 1] = to_tf32(bv.y);
            Bs[krow][nq + 2] = to_tf32(bv.z);
            Bs[krow][nq + 3] = to_tf32(bv.w);
        }
        __syncthreads();

#pragma unroll
        for (int ks = 0; ks < 32; ks += 8) {
            unsigned a[2][4];
#pragma unroll
            for (int mt = 0; mt < 2; mt++) {
                int r = wm * 32 + mt * 16 + (lane >> 2);
                int kc = ks + (lane & 3);
                a[mt][0] = As[r][kc];
                a[mt][1] = As[r + 8][kc];
                a[mt][2] = As[r][kc + 4];
                a[mt][3] = As[r + 8][kc + 4];
            }
#pragma unroll
            for (int nt = 0; nt < 8; nt++) {
                int col = wn * 64 + nt * 8 + (lane >> 2);
                int kc = ks + (lane & 3);
                unsigned b0 = Bs[kc][col];
                unsigned b1 = Bs[kc + 4][col];
#pragma unroll
                for (int mt = 0; mt < 2; mt++) {
                    asm volatile(
                        "mma.sync.aligned.m16n8k8.row.col.f32.tf32.tf32.f32 "
                        "{%0,%1,%2,%3}, {%4,%5,%6,%7}, {%8,%9}, {%0,%1,%2,%3};"
                        : "+f"(c[mt][nt][0]), "+f"(c[mt][nt][1]),
                          "+f"(c[mt][nt][2]), "+f"(c[mt][nt][3])
                        : "r"(a[mt][0]), "r"(a[mt][1]), "r"(a[mt][2]), "r"(a[mt][3]),
                          "r"(b0), "r"(b1));
                }
            }
        }
    }
    __syncthreads();

    // epilogue: bias + relu + store; BN partials in registers per column pair
    float s0[8][2], s2r[8][2];
#pragma unroll
    for (int nt = 0; nt < 8; nt++) {
        s0[nt][0] = 0.f; s0[nt][1] = 0.f;
        s2r[nt][0] = 0.f; s2r[nt][1] = 0.f;
    }
#pragma unroll
    for (int nt = 0; nt < 8; nt++) {
        int colb = wn * 64 + nt * 8 + (lane & 3) * 2;
        float b0 = mlp_b[colb], b1 = mlp_b[colb + 1];
#pragma unroll
        for (int mt = 0; mt < 2; mt++) {
            int rowa = row0 + wm * 32 + mt * 16 + (lane >> 2);
#pragma unroll
            for (int h = 0; h < 2; h++) {
                int row = rowa + h * 8;
                if (row >= n) continue;
                float y0 = c[mt][nt][h * 2 + 0] + b0;
                float y1 = c[mt][nt][h * 2 + 1] + b1;
                y0 = y0 > 0.f ? y0 : 0.f;
                y1 = y1 > 0.f ? y1 : 0.f;
                out[(size_t)row * F + colb] = y0;
                out[(size_t)row * F + colb + 1] = y1;
                s0[nt][0] += y0; s0[nt][1] += y1;
                s2r[nt][0] += y0 * y0; s2r[nt][1] += y1 * y1;
            }
        }
    }
#pragma unroll
    for (int nt = 0; nt < 8; nt++) {
        int colb = wn * 64 + nt * 8 + (lane & 3) * 2;
        atomicAdd(&ssum[colb], s0[nt][0]);
        atomicAdd(&ssum[colb + 1], s0[nt][1]);
        atomicAdd(&ssum2[colb], s2r[nt][0]);
        atomicAdd(&ssum2[colb + 1], s2r[nt][1]);
    }
    __syncthreads();
    if (tid < 128) {
        atomicAdd(&g_sum[tid], ssum[tid]);
        atomicAdd(&g_sum2[tid], ssum2[tid]);
    }
}

__global__ void k_bn(float* __restrict__ out, const float* __restrict__ gamma,
                     const float* __restrict__ beta, int n) {
    int i = blockIdx.x * blockDim.x + threadIdx.x;
    if (i >= n * F) return;
    int o = i & (F - 1);
    float inv_n = 1.f / (float)n;
    float mean = g_sum[o] * inv_n;
    float var = g_sum2[o] * inv_n - mean * mean;
    float y = out[i];
    out[i] = (y - mean) * rsqrtf(var + BN_EPS) * gamma[o] + beta[o];
}

// ---------------- launch ----------------
extern "C" void kernel_launch(void* const* d_in, const int* in_sizes, int n_in,
                              void* d_out, int out_size) {
    const float* feature = (const float*)d_in[0];
    const float* coords  = (const float*)d_in[1];
    const int*   src     = (const int*)d_in[2];
    const int*   dst     = (const int*)d_in[3];
    const int*   order   = (const int*)d_in[4];
    const float* linear  = (const float*)d_in[5];
    const float* attW    = (const float*)d_in[6];
    const float* mlp_w   = (const float*)d_in[7];
    const float* mlp_b   = (const float*)d_in[8];
    const float* bn_gamma = (const float*)d_in[9];
    const float* bn_beta  = (const float*)d_in[10];
    float* out = (float*)d_out;

    int n = in_sizes[0] / F;
    int e = in_sizes[2];
    int nb = (n + SCAN_B - 1) / SCAN_B;

    k_init<<<(n + 255) / 256, 256>>>(n);
    k_proj<<<(n * 32 + 255) / 256, 256>>>(feature, attW, n);

    int smemp = (128 * 129 + 16 * F) * (int)sizeof(float);
    cudaFuncSetAttribute(k_prep, cudaFuncAttributeMaxDynamicSharedMemorySize, smemp);
    k_prep<<<384 / 16, 128, smemp>>>(linear, mlp_w);

    k_edgeA<<<(e + 255) / 256, 256>>>(src, dst, coords, e);
    k_scan_block<<<nb, SCAN_B>>>(n);
    k_scan_top<<<1, 32>>>(nb);
    k_scan_add<<<nb, SCAN_B>>>(n, e);
    k_edgeB<<<(e + 255) / 256, 256>>>(src, dst, order, e);
    k_agg<<<(n * 32 + 255) / 256, 256>>>(feature, n);

    k_out_t<<<(n + 127) / 128, 256>>>(mlp_b, out, n);
    k_bn<<<(n * F + 255) / 256, 256>>>(out, bn_gamma, bn_beta, n);
}

// round 7
// speedup vs baseline: 1.4789x; 1.0904x over previous
#include <cuda_runtime.h>
#include <cuda_bf16.h>
#include <math.h>

#define NN 50000
#define EE 800000
#define F 128
#define BN_EPS 1e-5f
#define SCAN_B 1024
#define NBLK ((NN + SCAN_B - 1) / SCAN_B)

// ---------------- scratch ----------------
__device__ float g_agg[NN * 384];         // [n][k*128+o] aggregated features
__device__ float g_M[384 * 128];          // L @ W^T folded matrix
__device__ float g_proj[NN * 3];
__device__ float g_w[EE];                 // per-edge ex*inv
__device__ float g_den[NN];
__device__ float g_sum[F];
__device__ float g_sum2[F];
__device__ int   g_cnt[NN];
__device__ int   g_scan[NN];
__device__ int   g_bsum[NBLK];
__device__ int   g_off[NN + 1];
__device__ int   g_cur[NN];
__device__ long long g_pack[EE];          // {w (hi 32), src*4+order (lo 32)}

__device__ __forceinline__ unsigned to_tf32(float x) {
    unsigned r;
    asm("cvt.rna.tf32.f32 %0, %1;" : "=r"(r) : "f"(x));
    return r;
}

// ---------------- kernels ----------------
__global__ void k_init(int n) {
    int i = blockIdx.x * blockDim.x + threadIdx.x;
    if (i < n) { g_den[i] = 0.f; g_cnt[i] = 0; }
    if (i < F) { g_sum[i] = 0.f; g_sum2[i] = 0.f; }
}

__global__ void k_proj(const float* __restrict__ feat,
                       const float* __restrict__ attW, int n) {
    int w = (blockIdx.x * blockDim.x + threadIdx.x) >> 5;
    int lane = threadIdx.x & 31;
    if (w >= n) return;
    float4 f = reinterpret_cast<const float4*>(feat + (size_t)w * F)[lane];
    const float4* aw = reinterpret_cast<const float4*>(attW);
    float4 w0 = aw[lane], w1 = aw[32 + lane], w2 = aw[64 + lane];
    float a0 = f.x * w0.x + f.y * w0.y + f.z * w0.z + f.w * w0.w;
    float a1 = f.x * w1.x + f.y * w1.y + f.z * w1.z + f.w * w1.w;
    float a2 = f.x * w2.x + f.y * w2.y + f.z * w2.z + f.w * w2.w;
#pragma unroll
    for (int off = 16; off; off >>= 1) {
        a0 += __shfl_down_sync(0xffffffffu, a0, off);
        a1 += __shfl_down_sync(0xffffffffu, a1, off);
        a2 += __shfl_down_sync(0xffffffffu, a2, off);
    }
    if (lane == 0) {
        g_proj[w * 3 + 0] = a0; g_proj[w * 3 + 1] = a1; g_proj[w * 3 + 2] = a2;
    }
}

// single fused edge pass: att -> ex=exp(att) (no max; bounded), w=ex*inv,
// den += ex, cnt += 1
__global__ void k_edge1(const int* __restrict__ src, const int* __restrict__ dst,
                        const float* __restrict__ coords, int e) {
    int i = blockIdx.x * blockDim.x + threadIdx.x;
    if (i >= e) return;
    int s = src[i], d = dst[i];
    float dx = coords[s * 3 + 0] - coords[d * 3 + 0];
    float dy = coords[s * 3 + 1] - coords[d * 3 + 1];
    float dz = coords[s * 3 + 2] - coords[d * 3 + 2];
    float a = dx * g_proj[s * 3 + 0] + dy * g_proj[s * 3 + 1] + dz * g_proj[s * 3 + 2];
    float inv = 1.f / (dx * dx + dy * dy + dz * dz + 1.f);
    float ex = expf(a);
    g_w[i] = ex * inv;
    atomicAdd(&g_den[d], ex);
    atomicAdd(&g_cnt[d], 1);
}

__global__ void k_scan_block(int n) {
    __shared__ int s[SCAN_B];
    int g = blockIdx.x * SCAN_B + threadIdx.x;
    int v = (g < n) ? g_cnt[g] : 0;
    s[threadIdx.x] = v;
    __syncthreads();
#pragma unroll
    for (int off = 1; off < SCAN_B; off <<= 1) {
        int t = (threadIdx.x >= off) ? s[threadIdx.x - off] : 0;
        __syncthreads();
        s[threadIdx.x] += t;
        __syncthreads();
    }
    if (g < n) g_scan[g] = s[threadIdx.x];
    if (threadIdx.x == SCAN_B - 1) g_bsum[blockIdx.x] = s[SCAN_B - 1];
}
// block offsets computed inline (serial over <=49 bsums, L2 hits)
__global__ void k_scan_add(int n, int e) {
    __shared__ int sboff;
    if (threadIdx.x == 0) {
        int acc = 0;
        for (int i = 0; i < (int)blockIdx.x; i++) acc += g_bsum[i];
        sboff = acc;
    }
    __syncthreads();
    int g = blockIdx.x * SCAN_B + threadIdx.x;
    if (g < n) {
        int excl = g_scan[g] - g_cnt[g] + sboff;
        g_off[g] = excl;
        g_cur[g] = excl;
    }
    if (g == 0) g_off[n] = e;
}

// pack scatter into CSR slots
__global__ void k_edge2(const int* __restrict__ src, const int* __restrict__ dst,
                        const int* __restrict__ order, int e) {
    int i = blockIdx.x * blockDim.x + threadIdx.x;
    if (i >= e) return;
    int d = dst[i];
    int idx = src[i] * 4 + order[i];
    float w = g_w[i];
    int pos = atomicAdd(&g_cur[d], 1);
    g_pack[pos] = ((long long)__float_as_int(w) << 32) | (unsigned int)idx;
}

// aggregation: warp per dst, shfl-batched records, inner loop unrolled x4
__global__ void k_agg(const float* __restrict__ feat, int n) {
    int node = (blockIdx.x * blockDim.x + threadIdx.x) >> 5;
    int lane = threadIdx.x & 31;
    if (node >= n) return;
    int beg = g_off[node], end = g_off[node + 1];
    float den = g_den[node];
    float invden = 1.f / (den > 0.f ? den : 1.f);
    float4 a0 = make_float4(0.f, 0.f, 0.f, 0.f);
    float4 a1 = a0, a2 = a0;
    const float4* f4 = reinterpret_cast<const float4*>(feat);
    for (int base = beg; base < end; base += 32) {
        int idx = base + lane;
        long long pk = (idx < end) ? g_pack[idx] : 0;
        int cnt = min(32, end - base);
#pragma unroll 4
        for (int j = 0; j < cnt; j++) {
            long long p = __shfl_sync(0xffffffffu, pk, j);
            int id = (int)(unsigned int)p;
            int s = id >> 2, k = id & 3;
            float w = __int_as_float((int)(p >> 32)) * invden;
            float4 v = f4[(size_t)s * 32 + lane];
            if (k == 0) {
                a0.x += w * v.x; a0.y += w * v.y; a0.z += w * v.z; a0.w += w * v.w;
            } else if (k == 1) {
                a1.x += w * v.x; a1.y += w * v.y; a1.z += w * v.z; a1.w += w * v.w;
            } else {
                a2.x += w * v.x; a2.y += w * v.y; a2.z += w * v.z; a2.w += w * v.w;
            }
        }
    }
    float4* ap = reinterpret_cast<float4*>(g_agg + (size_t)node * 384);
    ap[lane] = a0;
    ap[32 + lane] = a1;
    ap[64 + lane] = a2;
}

// fold: M[r][o] = sum_j linear[r][j] * mlp_w[o][j]
__global__ void k_prep(const float* __restrict__ lin, const float* __restrict__ W) {
    extern __shared__ float smem[];
    float* swT = smem;              // [128][129]
    float* sL = smem + 128 * 129;   // [16][128]
    int t = threadIdx.x;
    int r0 = blockIdx.x * 16;
#pragma unroll 4
    for (int j = 0; j < F; j++)
        swT[t * 129 + j] = W[j * F + t];
    for (int idx = t; idx < 16 * F; idx += F)
        sL[idx] = lin[(size_t)r0 * F + idx];
    __syncthreads();
    float acc[16];
#pragma unroll
    for (int r = 0; r < 16; r++) acc[r] = 0.f;
#pragma unroll 4
    for (int j = 0; j < F; j++) {
        float wv = swT[j * 129 + t];
#pragma unroll
        for (int r = 0; r < 16; r++) acc[r] += sL[r * F + j] * wv;
    }
#pragma unroll
    for (int r = 0; r < 16; r++)
        g_M[(size_t)(r0 + r) * F + t] = acc[r];
}

// fused output GEMM (TF32 tensor cores, register-prefetch pipeline)
__global__ void __launch_bounds__(256, 1)
k_out_t(const float* __restrict__ mlp_b, float* __restrict__ out, int n) {
    __shared__ unsigned As[128][36];
    __shared__ unsigned Bs[32][132];
    __shared__ float ssum[128], ssum2[128];
    int tid = threadIdx.x;
    int lane = tid & 31;
    int wid = tid >> 5;
    int wm = wid >> 1;
    int wn = wid & 1;
    int row0 = blockIdx.x * 128;

    if (tid < 128) { ssum[tid] = 0.f; ssum2[tid] = 0.f; }

    float c[2][8][4];
#pragma unroll
    for (int i = 0; i < 2; i++)
#pragma unroll
        for (int j = 0; j < 8; j++)
#pragma unroll
            for (int q = 0; q < 4; q++) c[i][j][q] = 0.f;

    // per-thread load coordinates
    int arow[4], akq[4], brow[4], bnq[4];
#pragma unroll
    for (int i = 0; i < 4; i++) {
        int lidx = i * 256 + tid;
        arow[i] = lidx >> 3;  akq[i] = (lidx & 7) * 4;
        brow[i] = lidx >> 5;  bnq[i] = (lidx & 31) * 4;
    }

    float4 pa[4], pb[4];
    // prologue: load chunk 0
#pragma unroll
    for (int i = 0; i < 4; i++) {
        pa[i] = make_float4(0.f, 0.f, 0.f, 0.f);
        if (row0 + arow[i] < n)
            pa[i] = *reinterpret_cast<const float4*>(g_agg + (size_t)(row0 + arow[i]) * 384 + akq[i]);
        pb[i] = *reinterpret_cast<const float4*>(g_M + (size_t)brow[i] * F + bnq[i]);
    }

    for (int k0 = 0; k0 < 384; k0 += 32) {
        __syncthreads();
#pragma unroll
        for (int i = 0; i < 4; i++) {
            As[arow[i]][akq[i] + 0] = to_tf32(pa[i].x);
            As[arow[i]][akq[i] + 1] = to_tf32(pa[i].y);
            As[arow[i]][akq[i] + 2] = to_tf32(pa[i].z);
            As[arow[i]][akq[i] + 3] = to_tf32(pa[i].w);
            Bs[brow[i]][bnq[i] + 0] = to_tf32(pb[i].x);
            Bs[brow[i]][bnq[i] + 1] = to_tf32(pb[i].y);
            Bs[brow[i]][bnq[i] + 2] = to_tf32(pb[i].z);
            Bs[brow[i]][bnq[i] + 3] = to_tf32(pb[i].w);
        }
        __syncthreads();

        // prefetch next chunk while mma runs
        int kn = k0 + 32;
        if (kn < 384) {
#pragma unroll
            for (int i = 0; i < 4; i++) {
                pa[i] = make_float4(0.f, 0.f, 0.f, 0.f);
                if (row0 + arow[i] < n)
                    pa[i] = *reinterpret_cast<const float4*>(g_agg + (size_t)(row0 + arow[i]) * 384 + kn + akq[i]);
                pb[i] = *reinterpret_cast<const float4*>(g_M + (size_t)(kn + brow[i]) * F + bnq[i]);
            }
        }

#pragma unroll
        for (int ks = 0; ks < 32; ks += 8) {
            unsigned a[2][4];
#pragma unroll
            for (int mt = 0; mt < 2; mt++) {
                int r = wm * 32 + mt * 16 + (lane >> 2);
                int kc = ks + (lane & 3);
                a[mt][0] = As[r][kc];
                a[mt][1] = As[r + 8][kc];
                a[mt][2] = As[r][kc + 4];
                a[mt][3] = As[r + 8][kc + 4];
            }
#pragma unroll
            for (int nt = 0; nt < 8; nt++) {
                int col = wn * 64 + nt * 8 + (lane >> 2);
                int kc = ks + (lane & 3);
                unsigned b0 = Bs[kc][col];
                unsigned b1 = Bs[kc + 4][col];
#pragma unroll
                for (int mt = 0; mt < 2; mt++) {
                    asm volatile(
                        "mma.sync.aligned.m16n8k8.row.col.f32.tf32.tf32.f32 "
                        "{%0,%1,%2,%3}, {%4,%5,%6,%7}, {%8,%9}, {%0,%1,%2,%3};"
                        : "+f"(c[mt][nt][0]), "+f"(c[mt][nt][1]),
                          "+f"(c[mt][nt][2]), "+f"(c[mt][nt][3])
                        : "r"(a[mt][0]), "r"(a[mt][1]), "r"(a[mt][2]), "r"(a[mt][3]),
                          "r"(b0), "r"(b1));
                }
            }
        }
    }
    __syncthreads();

    // epilogue: bias + relu + store; BN partials in registers
    float s0[8][2], s2r[8][2];
#pragma unroll
    for (int nt = 0; nt < 8; nt++) {
        s0[nt][0] = 0.f; s0[nt][1] = 0.f;
        s2r[nt][0] = 0.f; s2r[nt][1] = 0.f;
    }
#pragma unroll
    for (int nt = 0; nt < 8; nt++) {
        int colb = wn * 64 + nt * 8 + (lane & 3) * 2;
        float b0 = mlp_b[colb], b1 = mlp_b[colb + 1];
#pragma unroll
        for (int mt = 0; mt < 2; mt++) {
            int rowa = row0 + wm * 32 + mt * 16 + (lane >> 2);
#pragma unroll
            for (int h = 0; h < 2; h++) {
                int row = rowa + h * 8;
                if (row >= n) continue;
                float y0 = c[mt][nt][h * 2 + 0] + b0;
                float y1 = c[mt][nt][h * 2 + 1] + b1;
                y0 = y0 > 0.f ? y0 : 0.f;
                y1 = y1 > 0.f ? y1 : 0.f;
                out[(size_t)row * F + colb] = y0;
                out[(size_t)row * F + colb + 1] = y1;
                s0[nt][0] += y0; s0[nt][1] += y1;
                s2r[nt][0] += y0 * y0; s2r[nt][1] += y1 * y1;
            }
        }
    }
#pragma unroll
    for (int nt = 0; nt < 8; nt++) {
        int colb = wn * 64 + nt * 8 + (lane & 3) * 2;
        atomicAdd(&ssum[colb], s0[nt][0]);
        atomicAdd(&ssum[colb + 1], s0[nt][1]);
        atomicAdd(&ssum2[colb], s2r[nt][0]);
        atomicAdd(&ssum2[colb + 1], s2r[nt][1]);
    }
    __syncthreads();
    if (tid < 128) {
        atomicAdd(&g_sum[tid], ssum[tid]);
        atomicAdd(&g_sum2[tid], ssum2[tid]);
    }
}

__global__ void k_bn(float* __restrict__ out, const float* __restrict__ gamma,
                     const float* __restrict__ beta, int n) {
    int i = blockIdx.x * blockDim.x + threadIdx.x;   // float4 index
    if (i >= n * 32) return;
    int ob = (i & 31) * 4;
    float inv_n = 1.f / (float)n;
    float4 y = reinterpret_cast<float4*>(out)[i];
    float m0 = g_sum[ob + 0] * inv_n, m1 = g_sum[ob + 1] * inv_n;
    float m2 = g_sum[ob + 2] * inv_n, m3 = g_sum[ob + 3] * inv_n;
    float v0 = g_sum2[ob + 0] * inv_n - m0 * m0;
    float v1 = g_sum2[ob + 1] * inv_n - m1 * m1;
    float v2 = g_sum2[ob + 2] * inv_n - m2 * m2;
    float v3 = g_sum2[ob + 3] * inv_n - m3 * m3;
    y.x = (y.x - m0) * rsqrtf(v0 + BN_EPS) * gamma[ob + 0] + beta[ob + 0];
    y.y = (y.y - m1) * rsqrtf(v1 + BN_EPS) * gamma[ob + 1] + beta[ob + 1];
    y.z = (y.z - m2) * rsqrtf(v2 + BN_EPS) * gamma[ob + 2] + beta[ob + 2];
    y.w = (y.w - m3) * rsqrtf(v3 + BN_EPS) * gamma[ob + 3] + beta[ob + 3];
    reinterpret_cast<float4*>(out)[i] = y;
}

// ---------------- launch ----------------
extern "C" void kernel_launch(void* const* d_in, const int* in_sizes, int n_in,
                              void* d_out, int out_size) {
    const float* feature = (const float*)d_in[0];
    const float* coords  = (const float*)d_in[1];
    const int*   src     = (const int*)d_in[2];
    const int*   dst     = (const int*)d_in[3];
    const int*   order   = (const int*)d_in[4];
    const float* linear  = (const float*)d_in[5];
    const float* attW    = (const float*)d_in[6];
    const float* mlp_w   = (const float*)d_in[7];
    const float* mlp_b   = (const float*)d_in[8];
    const float* bn_gamma = (const float*)d_in[9];
    const float* bn_beta  = (const float*)d_in[10];
    float* out = (float*)d_out;

    int n = in_sizes[0] / F;
    int e = in_sizes[2];
    int nb = (n + SCAN_B - 1) / SCAN_B;

    k_init<<<(n + 255) / 256, 256>>>(n);
    k_proj<<<(n * 32 + 255) / 256, 256>>>(feature, attW, n);

    int smemp = (128 * 129 + 16 * F) * (int)sizeof(float);
    cudaFuncSetAttribute(k_prep, cudaFuncAttributeMaxDynamicSharedMemorySize, smemp);
    k_prep<<<384 / 16, 128, smemp>>>(linear, mlp_w);

    k_edge1<<<(e + 255) / 256, 256>>>(src, dst, coords, e);
    k_scan_block<<<nb, SCAN_B>>>(n);
    k_scan_add<<<nb, SCAN_B>>>(n, e);
    k_edge2<<<(e + 255) / 256, 256>>>(src, dst, order, e);
    k_agg<<<(n * 32 + 255) / 256, 256>>>(feature, n);

    k_out_t<<<(n + 127) / 128, 256>>>(mlp_b, out, n);
    k_bn<<<(n * 32 + 255) / 256, 256>>>(out, bn_gamma, bn_beta, n);
}

// round 8
// speedup vs baseline: 1.5123x; 1.0226x over previous
#include <cuda_runtime.h>
#include <cuda_bf16.h>
#include <math.h>

#define NN 50000
#define EE 800000
#define F 128
#define BN_EPS 1e-5f
#define SCAN_B 1024
#define NBLK ((NN + SCAN_B - 1) / SCAN_B)

// ---------------- scratch ----------------
__device__ float g_agg[NN * 384];         // [n][k*128+o] aggregated features
__device__ float g_M[384 * 128];          // L @ W^T folded matrix
__device__ float4 g_cp[NN * 2];           // {cx,cy,cz,p0},{p1,p2,-,-} per node
__device__ float g_den[NN];
__device__ float g_sum[F];
__device__ float g_sum2[F];
__device__ int   g_cnt[NN];
__device__ int   g_rank[EE];
__device__ int   g_bsum[NBLK];
__device__ int   g_off[NN + 1];
__device__ long long g_tmp[EE];           // {w (hi), src*4+order (lo)} edge order
__device__ long long g_pack[EE];          // same, CSR order

__device__ __forceinline__ unsigned to_tf32(float x) {
    unsigned r;
    asm("cvt.rna.tf32.f32 %0, %1;" : "=r"(r) : "f"(x));
    return r;
}

// ---------------- kernels ----------------
__global__ void k_init(int n) {
    int i = blockIdx.x * blockDim.x + threadIdx.x;
    if (i < n) { g_den[i] = 0.f; g_cnt[i] = 0; }
    if (i < F) { g_sum[i] = 0.f; g_sum2[i] = 0.f; }
}

// per-node: proj = attW^T f; pack coords+proj into g_cp
__global__ void k_proj(const float* __restrict__ feat,
                       const float* __restrict__ coords,
                       const float* __restrict__ attW, int n) {
    int w = (blockIdx.x * blockDim.x + threadIdx.x) >> 5;
    int lane = threadIdx.x & 31;
    if (w >= n) return;
    float4 f = reinterpret_cast<const float4*>(feat + (size_t)w * F)[lane];
    const float4* aw = reinterpret_cast<const float4*>(attW);
    float4 w0 = aw[lane], w1 = aw[32 + lane], w2 = aw[64 + lane];
    float a0 = f.x * w0.x + f.y * w0.y + f.z * w0.z + f.w * w0.w;
    float a1 = f.x * w1.x + f.y * w1.y + f.z * w1.z + f.w * w1.w;
    float a2 = f.x * w2.x + f.y * w2.y + f.z * w2.z + f.w * w2.w;
#pragma unroll
    for (int off = 16; off; off >>= 1) {
        a0 += __shfl_down_sync(0xffffffffu, a0, off);
        a1 += __shfl_down_sync(0xffffffffu, a1, off);
        a2 += __shfl_down_sync(0xffffffffu, a2, off);
    }
    if (lane == 0) {
        float cx = coords[w * 3 + 0], cy = coords[w * 3 + 1], cz = coords[w * 3 + 2];
        g_cp[w * 2 + 0] = make_float4(cx, cy, cz, a0);
        g_cp[w * 2 + 1] = make_float4(a1, a2, 0.f, 0.f);
    }
}

// fused edge pass: w = exp(att)*inv, den+=ex, rank = cnt++ (hist), tmp record
__global__ void k_edge1(const int* __restrict__ src, const int* __restrict__ dst,
                        const int* __restrict__ order, int e) {
    int i = blockIdx.x * blockDim.x + threadIdx.x;
    if (i >= e) return;
    int s = src[i], d = dst[i];
    float4 cs0 = g_cp[s * 2 + 0];
    float4 cs1 = g_cp[s * 2 + 1];
    float4 cd0 = g_cp[d * 2 + 0];
    float dx = cs0.x - cd0.x, dy = cs0.y - cd0.y, dz = cs0.z - cd0.z;
    float a = dx * cs0.w + dy * cs1.x + dz * cs1.y;
    float inv = 1.f / (dx * dx + dy * dy + dz * dz + 1.f);
    float ex = expf(a);
    float w = ex * inv;
    atomicAdd(&g_den[d], ex);
    int rank = atomicAdd(&g_cnt[d], 1);
    g_rank[i] = rank;
    g_tmp[i] = ((long long)__float_as_int(w) << 32) | (unsigned int)(s * 4 + order[i]);
}

// exclusive block scan via warp shuffles (2 syncs)
__global__ void k_scan_block(int n) {
    __shared__ int swarp[32];
    int g = blockIdx.x * SCAN_B + threadIdx.x;
    int lane = threadIdx.x & 31;
    int wid = threadIdx.x >> 5;
    int v = (g < n) ? g_cnt[g] : 0;
    int x = v;
#pragma unroll
    for (int off = 1; off < 32; off <<= 1) {
        int t = __shfl_up_sync(0xffffffffu, x, off);
        if (lane >= off) x += t;
    }
    if (lane == 31) swarp[wid] = x;
    __syncthreads();
    if (wid == 0) {
        int y = swarp[lane];
#pragma unroll
        for (int off = 1; off < 32; off <<= 1) {
            int t = __shfl_up_sync(0xffffffffu, y, off);
            if (lane >= off) y += t;
        }
        swarp[lane] = y;
    }
    __syncthreads();
    int prefix = (wid > 0) ? swarp[wid - 1] : 0;
    int incl = x + prefix;
    if (g < n) g_off[g] = incl - v;            // exclusive within block
    if (threadIdx.x == SCAN_B - 1) g_bsum[blockIdx.x] = incl;
}
__global__ void k_scan_add(int n, int e) {
    __shared__ int sboff;
    if (threadIdx.x == 0) {
        int acc = 0;
        for (int i = 0; i < (int)blockIdx.x; i++) acc += g_bsum[i];
        sboff = acc;
    }
    __syncthreads();
    int g = blockIdx.x * SCAN_B + threadIdx.x;
    if (g < n) g_off[g] += sboff;
    if (g == 0) g_off[n] = e;
}

// pure permute into CSR order; no atomics
__global__ void k_edge2(const int* __restrict__ dst, int e) {
    int i = blockIdx.x * blockDim.x + threadIdx.x;
    if (i >= e) return;
    int pos = g_off[dst[i]] + g_rank[i];
    g_pack[pos] = g_tmp[i];
}

// aggregation: warp per dst, shfl-batched records, inner loop unrolled x4
__global__ void k_agg(const float* __restrict__ feat, int n) {
    int node = (blockIdx.x * blockDim.x + threadIdx.x) >> 5;
    int lane = threadIdx.x & 31;
    if (node >= n) return;
    int beg = g_off[node], end = g_off[node + 1];
    float den = g_den[node];
    float invden = 1.f / (den > 0.f ? den : 1.f);
    float4 a0 = make_float4(0.f, 0.f, 0.f, 0.f);
    float4 a1 = a0, a2 = a0;
    const float4* f4 = reinterpret_cast<const float4*>(feat);
    for (int base = beg; base < end; base += 32) {
        int idx = base + lane;
        long long pk = (idx < end) ? g_pack[idx] : 0;
        int cnt = min(32, end - base);
#pragma unroll 4
        for (int j = 0; j < cnt; j++) {
            long long p = __shfl_sync(0xffffffffu, pk, j);
            int id = (int)(unsigned int)p;
            int s = id >> 2, k = id & 3;
            float w = __int_as_float((int)(p >> 32)) * invden;
            float4 v = f4[(size_t)s * 32 + lane];
            if (k == 0) {
                a0.x += w * v.x; a0.y += w * v.y; a0.z += w * v.z; a0.w += w * v.w;
            } else if (k == 1) {
                a1.x += w * v.x; a1.y += w * v.y; a1.z += w * v.z; a1.w += w * v.w;
            } else {
                a2.x += w * v.x; a2.y += w * v.y; a2.z += w * v.z; a2.w += w * v.w;
            }
        }
    }
    float4* ap = reinterpret_cast<float4*>(g_agg + (size_t)node * 384);
    ap[lane] = a0;
    ap[32 + lane] = a1;
    ap[64 + lane] = a2;
}

// fold: M[r][o] = sum_j linear[r][j] * mlp_w[o][j]
__global__ void k_prep(const float* __restrict__ lin, const float* __restrict__ W) {
    extern __shared__ float smem[];
    float* swT = smem;              // [128][129]
    float* sL = smem + 128 * 129;   // [16][128]
    int t = threadIdx.x;
    int r0 = blockIdx.x * 16;
#pragma unroll 4
    for (int j = 0; j < F; j++)
        swT[t * 129 + j] = W[j * F + t];
    for (int idx = t; idx < 16 * F; idx += F)
        sL[idx] = lin[(size_t)r0 * F + idx];
    __syncthreads();
    float acc[16];
#pragma unroll
    for (int r = 0; r < 16; r++) acc[r] = 0.f;
#pragma unroll 4
    for (int j = 0; j < F; j++) {
        float wv = swT[j * 129 + t];
#pragma unroll
        for (int r = 0; r < 16; r++) acc[r] += sL[r * F + j] * wv;
    }
#pragma unroll
    for (int r = 0; r < 16; r++)
        g_M[(size_t)(r0 + r) * F + t] = acc[r];
}

// fused output GEMM (TF32 tensor cores, register-prefetch pipeline)
__global__ void __launch_bounds__(256, 1)
k_out_t(const float* __restrict__ mlp_b, float* __restrict__ out, int n) {
    __shared__ unsigned As[128][36];
    __shared__ unsigned Bs[32][132];
    __shared__ float ssum[128], ssum2[128];
    int tid = threadIdx.x;
    int lane = tid & 31;
    int wid = tid >> 5;
    int wm = wid >> 1;
    int wn = wid & 1;
    int row0 = blockIdx.x * 128;

    if (tid < 128) { ssum[tid] = 0.f; ssum2[tid] = 0.f; }

    float c[2][8][4];
#pragma unroll
    for (int i = 0; i < 2; i++)
#pragma unroll
        for (int j = 0; j < 8; j++)
#pragma unroll
            for (int q = 0; q < 4; q++) c[i][j][q] = 0.f;

    int arow[4], akq[4], brow[4], bnq[4];
#pragma unroll
    for (int i = 0; i < 4; i++) {
        int lidx = i * 256 + tid;
        arow[i] = lidx >> 3;  akq[i] = (lidx & 7) * 4;
        brow[i] = lidx >> 5;  bnq[i] = (lidx & 31) * 4;
    }

    float4 pa[4], pb[4];
#pragma unroll
    for (int i = 0; i < 4; i++) {
        pa[i] = make_float4(0.f, 0.f, 0.f, 0.f);
        if (row0 + arow[i] < n)
            pa[i] = *reinterpret_cast<const float4*>(g_agg + (size_t)(row0 + arow[i]) * 384 + akq[i]);
        pb[i] = *reinterpret_cast<const float4*>(g_M + (size_t)brow[i] * F + bnq[i]);
    }

    for (int k0 = 0; k0 < 384; k0 += 32) {
        __syncthreads();
#pragma unroll
        for (int i = 0; i < 4; i++) {
            As[arow[i]][akq[i] + 0] = to_tf32(pa[i].x);
            As[arow[i]][akq[i] + 1] = to_tf32(pa[i].y);
            As[arow[i]][akq[i] + 2] = to_tf32(pa[i].z);
            As[arow[i]][akq[i] + 3] = to_tf32(pa[i].w);
            Bs[brow[i]][bnq[i] + 0] = to_tf32(pb[i].x);
            Bs[brow[i]][bnq[i] + 1] = to_tf32(pb[i].y);
            Bs[brow[i]][bnq[i] + 2] = to_tf32(pb[i].z);
            Bs[brow[i]][bnq[i] + 3] = to_tf32(pb[i].w);
        }
        __syncthreads();

        int kn = k0 + 32;
        if (kn < 384) {
#pragma unroll
            for (int i = 0; i < 4; i++) {
                pa[i] = make_float4(0.f, 0.f, 0.f, 0.f);
                if (row0 + arow[i] < n)
                    pa[i] = *reinterpret_cast<const float4*>(g_agg + (size_t)(row0 + arow[i]) * 384 + kn + akq[i]);
                pb[i] = *reinterpret_cast<const float4*>(g_M + (size_t)(kn + brow[i]) * F + bnq[i]);
            }
        }

#pragma unroll
        for (int ks = 0; ks < 32; ks += 8) {
            unsigned a[2][4];
#pragma unroll
            for (int mt = 0; mt < 2; mt++) {
                int r = wm * 32 + mt * 16 + (lane >> 2);
                int kc = ks + (lane & 3);
                a[mt][0] = As[r][kc];
                a[mt][1] = As[r + 8][kc];
                a[mt][2] = As[r][kc + 4];
                a[mt][3] = As[r + 8][kc + 4];
            }
#pragma unroll
            for (int nt = 0; nt < 8; nt++) {
                int col = wn * 64 + nt * 8 + (lane >> 2);
                int kc = ks + (lane & 3);
                unsigned b0 = Bs[kc][col];
                unsigned b1 = Bs[kc + 4][col];
#pragma unroll
                for (int mt = 0; mt < 2; mt++) {
                    asm volatile(
                        "mma.sync.aligned.m16n8k8.row.col.f32.tf32.tf32.f32 "
                        "{%0,%1,%2,%3}, {%4,%5,%6,%7}, {%8,%9}, {%0,%1,%2,%3};"
                        : "+f"(c[mt][nt][0]), "+f"(c[mt][nt][1]),
                          "+f"(c[mt][nt][2]), "+f"(c[mt][nt][3])
                        : "r"(a[mt][0]), "r"(a[mt][1]), "r"(a[mt][2]), "r"(a[mt][3]),
                          "r"(b0), "r"(b1));
                }
            }
        }
    }
    __syncthreads();

    float s0[8][2], s2r[8][2];
#pragma unroll
    for (int nt = 0; nt < 8; nt++) {
        s0[nt][0] = 0.f; s0[nt][1] = 0.f;
        s2r[nt][0] = 0.f; s2r[nt][1] = 0.f;
    }
#pragma unroll
    for (int nt = 0; nt < 8; nt++) {
        int colb = wn * 64 + nt * 8 + (lane & 3) * 2;
        float b0 = mlp_b[colb], b1 = mlp_b[colb + 1];
#pragma unroll
        for (int mt = 0; mt < 2; mt++) {
            int rowa = row0 + wm * 32 + mt * 16 + (lane >> 2);
#pragma unroll
            for (int h = 0; h < 2; h++) {
                int row = rowa + h * 8;
                if (row >= n) continue;
                float y0 = c[mt][nt][h * 2 + 0] + b0;
                float y1 = c[mt][nt][h * 2 + 1] + b1;
                y0 = y0 > 0.f ? y0 : 0.f;
                y1 = y1 > 0.f ? y1 : 0.f;
                out[(size_t)row * F + colb] = y0;
                out[(size_t)row * F + colb + 1] = y1;
                s0[nt][0] += y0; s0[nt][1] += y1;
                s2r[nt][0] += y0 * y0; s2r[nt][1] += y1 * y1;
            }
        }
    }
#pragma unroll
    for (int nt = 0; nt < 8; nt++) {
        int colb = wn * 64 + nt * 8 + (lane & 3) * 2;
        atomicAdd(&ssum[colb], s0[nt][0]);
        atomicAdd(&ssum[colb + 1], s0[nt][1]);
        atomicAdd(&ssum2[colb], s2r[nt][0]);
        atomicAdd(&ssum2[colb + 1], s2r[nt][1]);
    }
    __syncthreads();
    if (tid < 128) {
        atomicAdd(&g_sum[tid], ssum[tid]);
        atomicAdd(&g_sum2[tid], ssum2[tid]);
    }
}

__global__ void k_bn(float* __restrict__ out, const float* __restrict__ gamma,
                     const float* __restrict__ beta, int n) {
    int i = blockIdx.x * blockDim.x + threadIdx.x;   // float4 index
    if (i >= n * 32) return;
    int ob = (i & 31) * 4;
    float inv_n = 1.f / (float)n;
    float4 y = reinterpret_cast<float4*>(out)[i];
    float m0 = g_sum[ob + 0] * inv_n, m1 = g_sum[ob + 1] * inv_n;
    float m2 = g_sum[ob + 2] * inv_n, m3 = g_sum[ob + 3] * inv_n;
    float v0 = g_sum2[ob + 0] * inv_n - m0 * m0;
    float v1 = g_sum2[ob + 1] * inv_n - m1 * m1;
    float v2 = g_sum2[ob + 2] * inv_n - m2 * m2;
    float v3 = g_sum2[ob + 3] * inv_n - m3 * m3;
    y.x = (y.x - m0) * rsqrtf(v0 + BN_EPS) * gamma[ob + 0] + beta[ob + 0];
    y.y = (y.y - m1) * rsqrtf(v1 + BN_EPS) * gamma[ob + 1] + beta[ob + 1];
    y.z = (y.z - m2) * rsqrtf(v2 + BN_EPS) * gamma[ob + 2] + beta[ob + 2];
    y.w = (y.w - m3) * rsqrtf(v3 + BN_EPS) * gamma[ob + 3] + beta[ob + 3];
    reinterpret_cast<float4*>(out)[i] = y;
}

// ---------------- launch ----------------
extern "C" void kernel_launch(void* const* d_in, const int* in_sizes, int n_in,
                              void* d_out, int out_size) {
    const float* feature = (const float*)d_in[0];
    const float* coords  = (const float*)d_in[1];
    const int*   src     = (const int*)d_in[2];
    const int*   dst     = (const int*)d_in[3];
    const int*   order   = (const int*)d_in[4];
    const float* linear  = (const float*)d_in[5];
    const float* attW    = (const float*)d_in[6];
    const float* mlp_w   = (const float*)d_in[7];
    const float* mlp_b   = (const float*)d_in[8];
    const float* bn_gamma = (const float*)d_in[9];
    const float* bn_beta  = (const float*)d_in[10];
    float* out = (float*)d_out;

    int n = in_sizes[0] / F;
    int e = in_sizes[2];
    int nb = (n + SCAN_B - 1) / SCAN_B;

    k_init<<<(n + 255) / 256, 256>>>(n);
    k_proj<<<(n * 32 + 255) / 256, 256>>>(feature, coords, attW, n);

    int smemp = (128 * 129 + 16 * F) * (int)sizeof(float);
    cudaFuncSetAttribute(k_prep, cudaFuncAttributeMaxDynamicSharedMemorySize, smemp);
    k_prep<<<384 / 16, 128, smemp>>>(linear, mlp_w);

    k_edge1<<<(e + 255) / 256, 256>>>(src, dst, order, e);
    k_scan_block<<<nb, SCAN_B>>>(n);
    k_scan_add<<<nb, SCAN_B>>>(n, e);
    k_edge2<<<(e + 255) / 256, 256>>>(dst, e);
    k_agg<<<(n * 32 + 255) / 256, 256>>>(feature, n);

    k_out_t<<<(n + 127) / 128, 256>>>(mlp_b, out, n);
    k_bn<<<(n * 32 + 255) / 256, 256>>>(out, bn_gamma, bn_beta, n);
}

// round 9
// speedup vs baseline: 1.5247x; 1.0082x over previous
#include <cuda_runtime.h>
#include <cuda_bf16.h>
#include <math.h>

#define NN 50000
#define EE 800000
#define F 128
#define BN_EPS 1e-5f
#define SCAN_B 1024
#define NBLK ((NN + SCAN_B - 1) / SCAN_B)

// ---------------- scratch ----------------
__device__ float g_agg[NN * 384];         // [n][k*128+o] aggregated features
__device__ float g_M[384 * 128];          // L @ W^T folded matrix
__device__ float4 g_cp[NN * 2];           // {cx,cy,cz,p0},{p1,p2,-,-} per node
__device__ float g_sum[F];
__device__ float g_sum2[F];
__device__ int   g_cnt[NN];
__device__ int   g_rank[EE];
__device__ int   g_bsum[NBLK];
__device__ int   g_off[NN + 1];
__device__ long long g_tmp[EE];           // {w (hi), src*4+order (lo)} edge order
__device__ float g_extmp[EE];             // ex, edge order
__device__ long long g_pack[EE];          // CSR order
__device__ float g_ex[EE];                // ex, CSR order

__device__ __forceinline__ unsigned to_tf32(float x) {
    unsigned r;
    asm("cvt.rna.tf32.f32 %0, %1;" : "=r"(r) : "f"(x));
    return r;
}

// ---------------- kernels ----------------
// per-node: proj = attW^T f; pack coords+proj; zero cnt
__global__ void k_proj(const float* __restrict__ feat,
                       const float* __restrict__ coords,
                       const float* __restrict__ attW, int n) {
    int w = (blockIdx.x * blockDim.x + threadIdx.x) >> 5;
    int lane = threadIdx.x & 31;
    if (w >= n) return;
    float4 f = reinterpret_cast<const float4*>(feat + (size_t)w * F)[lane];
    const float4* aw = reinterpret_cast<const float4*>(attW);
    float4 w0 = aw[lane], w1 = aw[32 + lane], w2 = aw[64 + lane];
    float a0 = f.x * w0.x + f.y * w0.y + f.z * w0.z + f.w * w0.w;
    float a1 = f.x * w1.x + f.y * w1.y + f.z * w1.z + f.w * w1.w;
    float a2 = f.x * w2.x + f.y * w2.y + f.z * w2.z + f.w * w2.w;
#pragma unroll
    for (int off = 16; off; off >>= 1) {
        a0 += __shfl_down_sync(0xffffffffu, a0, off);
        a1 += __shfl_down_sync(0xffffffffu, a1, off);
        a2 += __shfl_down_sync(0xffffffffu, a2, off);
    }
    if (lane == 0) {
        float cx = coords[w * 3 + 0], cy = coords[w * 3 + 1], cz = coords[w * 3 + 2];
        g_cp[w * 2 + 0] = make_float4(cx, cy, cz, a0);
        g_cp[w * 2 + 1] = make_float4(a1, a2, 0.f, 0.f);
        g_cnt[w] = 0;
    }
}

// fused edge pass: ex=exp(att), w=ex*inv, rank=cnt++ (ONLY atomic), tmp records
__global__ void k_edge1(const int* __restrict__ src, const int* __restrict__ dst,
                        const int* __restrict__ order, int e) {
    int i = blockIdx.x * blockDim.x + threadIdx.x;
    if (i >= e) return;
    int s = src[i], d = dst[i];
    float4 cs0 = g_cp[s * 2 + 0];
    float4 cs1 = g_cp[s * 2 + 1];
    float4 cd0 = g_cp[d * 2 + 0];
    float dx = cs0.x - cd0.x, dy = cs0.y - cd0.y, dz = cs0.z - cd0.z;
    float a = dx * cs0.w + dy * cs1.x + dz * cs1.y;
    float inv = 1.f / (dx * dx + dy * dy + dz * dz + 1.f);
    float ex = __expf(a);
    float w = ex * inv;
    int rank = atomicAdd(&g_cnt[d], 1);
    g_rank[i] = rank;
    g_extmp[i] = ex;
    g_tmp[i] = ((long long)__float_as_int(w) << 32) | (unsigned int)(s * 4 + order[i]);
}

// exclusive block scan via warp shuffles
__global__ void k_scan_block(int n) {
    __shared__ int swarp[32];
    int g = blockIdx.x * SCAN_B + threadIdx.x;
    int lane = threadIdx.x & 31;
    int wid = threadIdx.x >> 5;
    int v = (g < n) ? g_cnt[g] : 0;
    int x = v;
#pragma unroll
    for (int off = 1; off < 32; off <<= 1) {
        int t = __shfl_up_sync(0xffffffffu, x, off);
        if (lane >= off) x += t;
    }
    if (lane == 31) swarp[wid] = x;
    __syncthreads();
    if (wid == 0) {
        int y = swarp[lane];
#pragma unroll
        for (int off = 1; off < 32; off <<= 1) {
            int t = __shfl_up_sync(0xffffffffu, y, off);
            if (lane >= off) y += t;
        }
        swarp[lane] = y;
    }
    __syncthreads();
    int prefix = (wid > 0) ? swarp[wid - 1] : 0;
    int incl = x + prefix;
    if (g < n) g_off[g] = incl - v;
    if (threadIdx.x == SCAN_B - 1) g_bsum[blockIdx.x] = incl;
}
__global__ void k_scan_add(int n, int e) {
    __shared__ int sboff;
    if (threadIdx.x == 0) {
        int acc = 0;
        for (int i = 0; i < (int)blockIdx.x; i++) acc += g_bsum[i];
        sboff = acc;
    }
    __syncthreads();
    int g = blockIdx.x * SCAN_B + threadIdx.x;
    if (g < n) g_off[g] += sboff;
    if (g == 0) g_off[n] = e;
}

// pure permute into CSR order; no atomics
__global__ void k_edge2(const int* __restrict__ dst, int e) {
    int i = blockIdx.x * blockDim.x + threadIdx.x;
    if (i >= e) return;
    int pos = g_off[dst[i]] + g_rank[i];
    g_pack[pos] = g_tmp[i];
    g_ex[pos] = g_extmp[i];
}

// aggregation: warp per dst; records staged via smem (no shfl), den computed
// in-warp, normalization applied once at store. No atomics.
__global__ void k_agg(const float* __restrict__ feat, int n) {
    __shared__ long long srec[8][33];
    int wwid = threadIdx.x >> 5;
    int node = (blockIdx.x * blockDim.x + threadIdx.x) >> 5;
    int lane = threadIdx.x & 31;
    if (node >= n) return;
    int beg = g_off[node], end = g_off[node + 1];
    float4 a0 = make_float4(0.f, 0.f, 0.f, 0.f);
    float4 a1 = a0, a2 = a0;
    float densum = 0.f;
    const float4* f4 = reinterpret_cast<const float4*>(feat);
    for (int base = beg; base < end; base += 32) {
        int idx = base + lane;
        if (idx < end) {
            srec[wwid][lane] = g_pack[idx];
            densum += g_ex[idx];
        }
        __syncwarp();
        int cnt = min(32, end - base);
#pragma unroll 4
        for (int j = 0; j < cnt; j++) {
            long long p = srec[wwid][j];           // uniform LDS -> broadcast
            int id = (int)(unsigned int)p;
            int s = id >> 2, k = id & 3;
            float w = __int_as_float((int)(p >> 32));
            float4 v = f4[(size_t)s * 32 + lane];
            if (k == 0) {
                a0.x += w * v.x; a0.y += w * v.y; a0.z += w * v.z; a0.w += w * v.w;
            } else if (k == 1) {
                a1.x += w * v.x; a1.y += w * v.y; a1.z += w * v.z; a1.w += w * v.w;
            } else {
                a2.x += w * v.x; a2.y += w * v.y; a2.z += w * v.z; a2.w += w * v.w;
            }
        }
        __syncwarp();
    }
    // warp-reduce densum
#pragma unroll
    for (int off = 16; off; off >>= 1)
        densum += __shfl_down_sync(0xffffffffu, densum, off);
    float den = __shfl_sync(0xffffffffu, densum, 0);
    float invden = 1.f / (den > 0.f ? den : 1.f);
    a0.x *= invden; a0.y *= invden; a0.z *= invden; a0.w *= invden;
    a1.x *= invden; a1.y *= invden; a1.z *= invden; a1.w *= invden;
    a2.x *= invden; a2.y *= invden; a2.z *= invden; a2.w *= invden;
    float4* ap = reinterpret_cast<float4*>(g_agg + (size_t)node * 384);
    ap[lane] = a0;
    ap[32 + lane] = a1;
    ap[64 + lane] = a2;
}

// fold: M[r][o] = sum_j linear[r][j] * mlp_w[o][j]; block 0 zeros BN sums
__global__ void k_prep(const float* __restrict__ lin, const float* __restrict__ W) {
    extern __shared__ float smem[];
    float* swT = smem;              // [128][129]
    float* sL = smem + 128 * 129;   // [16][128]
    int t = threadIdx.x;
    int r0 = blockIdx.x * 16;
    if (blockIdx.x == 0) { g_sum[t] = 0.f; g_sum2[t] = 0.f; }
#pragma unroll 4
    for (int j = 0; j < F; j++)
        swT[t * 129 + j] = W[j * F + t];
    for (int idx = t; idx < 16 * F; idx += F)
        sL[idx] = lin[(size_t)r0 * F + idx];
    __syncthreads();
    float acc[16];
#pragma unroll
    for (int r = 0; r < 16; r++) acc[r] = 0.f;
#pragma unroll 4
    for (int j = 0; j < F; j++) {
        float wv = swT[j * 129 + t];
#pragma unroll
        for (int r = 0; r < 16; r++) acc[r] += sL[r * F + j] * wv;
    }
#pragma unroll
    for (int r = 0; r < 16; r++)
        g_M[(size_t)(r0 + r) * F + t] = acc[r];
}

// fused output GEMM (TF32 tensor cores, register-prefetch pipeline)
__global__ void __launch_bounds__(256, 1)
k_out_t(const float* __restrict__ mlp_b, float* __restrict__ out, int n) {
    __shared__ unsigned As[128][36];
    __shared__ unsigned Bs[32][132];
    __shared__ float ssum[128], ssum2[128];
    int tid = threadIdx.x;
    int lane = tid & 31;
    int wid = tid >> 5;
    int wm = wid >> 1;
    int wn = wid & 1;
    int row0 = blockIdx.x * 128;

    if (tid < 128) { ssum[tid] = 0.f; ssum2[tid] = 0.f; }

    float c[2][8][4];
#pragma unroll
    for (int i = 0; i < 2; i++)
#pragma unroll
        for (int j = 0; j < 8; j++)
#pragma unroll
            for (int q = 0; q < 4; q++) c[i][j][q] = 0.f;

    int arow[4], akq[4], brow[4], bnq[4];
#pragma unroll
    for (int i = 0; i < 4; i++) {
        int lidx = i * 256 + tid;
        arow[i] = lidx >> 3;  akq[i] = (lidx & 7) * 4;
        brow[i] = lidx >> 5;  bnq[i] = (lidx & 31) * 4;
    }

    float4 pa[4], pb[4];
#pragma unroll
    for (int i = 0; i < 4; i++) {
        pa[i] = make_float4(0.f, 0.f, 0.f, 0.f);
        if (row0 + arow[i] < n)
            pa[i] = *reinterpret_cast<const float4*>(g_agg + (size_t)(row0 + arow[i]) * 384 + akq[i]);
        pb[i] = *reinterpret_cast<const float4*>(g_M + (size_t)brow[i] * F + bnq[i]);
    }

    for (int k0 = 0; k0 < 384; k0 += 32) {
        __syncthreads();
#pragma unroll
        for (int i = 0; i < 4; i++) {
            As[arow[i]][akq[i] + 0] = to_tf32(pa[i].x);
            As[arow[i]][akq[i] + 1] = to_tf32(pa[i].y);
            As[arow[i]][akq[i] + 2] = to_tf32(pa[i].z);
            As[arow[i]][akq[i] + 3] = to_tf32(pa[i].w);
            Bs[brow[i]][bnq[i] + 0] = to_tf32(pb[i].x);
            Bs[brow[i]][bnq[i] + 1] = to_tf32(pb[i].y);
            Bs[brow[i]][bnq[i] + 2] = to_tf32(pb[i].z);
            Bs[brow[i]][bnq[i] + 3] = to_tf32(pb[i].w);
        }
        __syncthreads();

        int kn = k0 + 32;
        if (kn < 384) {
#pragma unroll
            for (int i = 0; i < 4; i++) {
                pa[i] = make_float4(0.f, 0.f, 0.f, 0.f);
                if (row0 + arow[i] < n)
                    pa[i] = *reinterpret_cast<const float4*>(g_agg + (size_t)(row0 + arow[i]) * 384 + kn + akq[i]);
                pb[i] = *reinterpret_cast<const float4*>(g_M + (size_t)(kn + brow[i]) * F + bnq[i]);
            }
        }

#pragma unroll
        for (int ks = 0; ks < 32; ks += 8) {
            unsigned a[2][4];
#pragma unroll
            for (int mt = 0; mt < 2; mt++) {
                int r = wm * 32 + mt * 16 + (lane >> 2);
                int kc = ks + (lane & 3);
                a[mt][0] = As[r][kc];
                a[mt][1] = As[r + 8][kc];
                a[mt][2] = As[r][kc + 4];
                a[mt][3] = As[r + 8][kc + 4];
            }
#pragma unroll
            for (int nt = 0; nt < 8; nt++) {
                int col = wn * 64 + nt * 8 + (lane >> 2);
                int kc = ks + (lane & 3);
                unsigned b0 = Bs[kc][col];
                unsigned b1 = Bs[kc + 4][col];
#pragma unroll
                for (int mt = 0; mt < 2; mt++) {
                    asm volatile(
                        "mma.sync.aligned.m16n8k8.row.col.f32.tf32.tf32.f32 "
                        "{%0,%1,%2,%3}, {%4,%5,%6,%7}, {%8,%9}, {%0,%1,%2,%3};"
                        : "+f"(c[mt][nt][0]), "+f"(c[mt][nt][1]),
                          "+f"(c[mt][nt][2]), "+f"(c[mt][nt][3])
                        : "r"(a[mt][0]), "r"(a[mt][1]), "r"(a[mt][2]), "r"(a[mt][3]),
                          "r"(b0), "r"(b1));
                }
            }
        }
    }
    __syncthreads();

    float s0[8][2], s2r[8][2];
#pragma unroll
    for (int nt = 0; nt < 8; nt++) {
        s0[nt][0] = 0.f; s0[nt][1] = 0.f;
        s2r[nt][0] = 0.f; s2r[nt][1] = 0.f;
    }
#pragma unroll
    for (int nt = 0; nt < 8; nt++) {
        int colb = wn * 64 + nt * 8 + (lane & 3) * 2;
        float b0 = mlp_b[colb], b1 = mlp_b[colb + 1];
#pragma unroll
        for (int mt = 0; mt < 2; mt++) {
            int rowa = row0 + wm * 32 + mt * 16 + (lane >> 2);
#pragma unroll
            for (int h = 0; h < 2; h++) {
                int row = rowa + h * 8;
                if (row >= n) continue;
                float y0 = c[mt][nt][h * 2 + 0] + b0;
                float y1 = c[mt][nt][h * 2 + 1] + b1;
                y0 = y0 > 0.f ? y0 : 0.f;
                y1 = y1 > 0.f ? y1 : 0.f;
                out[(size_t)row * F + colb] = y0;
                out[(size_t)row * F + colb + 1] = y1;
                s0[nt][0] += y0; s0[nt][1] += y1;
                s2r[nt][0] += y0 * y0; s2r[nt][1] += y1 * y1;
            }
        }
    }
#pragma unroll
    for (int nt = 0; nt < 8; nt++) {
        int colb = wn * 64 + nt * 8 + (lane & 3) * 2;
        atomicAdd(&ssum[colb], s0[nt][0]);
        atomicAdd(&ssum[colb + 1], s0[nt][1]);
        atomicAdd(&ssum2[colb], s2r[nt][0]);
        atomicAdd(&ssum2[colb + 1], s2r[nt][1]);
    }
    __syncthreads();
    if (tid < 128) {
        atomicAdd(&g_sum[tid], ssum[tid]);
        atomicAdd(&g_sum2[tid], ssum2[tid]);
    }
}

__global__ void k_bn(float* __restrict__ out, const float* __restrict__ gamma,
                     const float* __restrict__ beta, int n) {
    int i = blockIdx.x * blockDim.x + threadIdx.x;   // float4 index
    if (i >= n * 32) return;
    int ob = (i & 31) * 4;
    float inv_n = 1.f / (float)n;
    float4 y = reinterpret_cast<float4*>(out)[i];
    float m0 = g_sum[ob + 0] * inv_n, m1 = g_sum[ob + 1] * inv_n;
    float m2 = g_sum[ob + 2] * inv_n, m3 = g_sum[ob + 3] * inv_n;
    float v0 = g_sum2[ob + 0] * inv_n - m0 * m0;
    float v1 = g_sum2[ob + 1] * inv_n - m1 * m1;
    float v2 = g_sum2[ob + 2] * inv_n - m2 * m2;
    float v3 = g_sum2[ob + 3] * inv_n - m3 * m3;
    y.x = (y.x - m0) * rsqrtf(v0 + BN_EPS) * gamma[ob + 0] + beta[ob + 0];
    y.y = (y.y - m1) * rsqrtf(v1 + BN_EPS) * gamma[ob + 1] + beta[ob + 1];
    y.z = (y.z - m2) * rsqrtf(v2 + BN_EPS) * gamma[ob + 2] + beta[ob + 2];
    y.w = (y.w - m3) * rsqrtf(v3 + BN_EPS) * gamma[ob + 3] + beta[ob + 3];
    reinterpret_cast<float4*>(out)[i] = y;
}

// ---------------- launch ----------------
extern "C" void kernel_launch(void* const* d_in, const int* in_sizes, int n_in,
                              void* d_out, int out_size) {
    const float* feature = (const float*)d_in[0];
    const float* coords  = (const float*)d_in[1];
    const int*   src     = (const int*)d_in[2];
    const int*   dst     = (const int*)d_in[3];
    const int*   order   = (const int*)d_in[4];
    const float* linear  = (const float*)d_in[5];
    const float* attW    = (const float*)d_in[6];
    const float* mlp_w   = (const float*)d_in[7];
    const float* mlp_b   = (const float*)d_in[8];
    const float* bn_gamma = (const float*)d_in[9];
    const float* bn_beta  = (const float*)d_in[10];
    float* out = (float*)d_out;

    int n = in_sizes[0] / F;
    int e = in_sizes[2];
    int nb = (n + SCAN_B - 1) / SCAN_B;

    k_proj<<<(n * 32 + 255) / 256, 256>>>(feature, coords, attW, n);

    int smemp = (128 * 129 + 16 * F) * (int)sizeof(float);
    cudaFuncSetAttribute(k_prep, cudaFuncAttributeMaxDynamicSharedMemorySize, smemp);
    k_prep<<<384 / 16, 128, smemp>>>(linear, mlp_w);

    k_edge1<<<(e + 255) / 256, 256>>>(src, dst, order, e);
    k_scan_block<<<nb, SCAN_B>>>(n);
    k_scan_add<<<nb, SCAN_B>>>(n, e);
    k_edge2<<<(e + 255) / 256, 256>>>(dst, e);
    k_agg<<<(n * 32 + 255) / 256, 256>>>(feature, n);

    k_out_t<<<(n + 127) / 128, 256>>>(mlp_b, out, n);
    k_bn<<<(n * 32 + 255) / 256, 256>>>(out, bn_gamma, bn_beta, n);
}

// round 10
// speedup vs baseline: 1.7027x; 1.1167x over previous
#include <cuda_runtime.h>
#include <cuda_bf16.h>
#include <cuda_fp16.h>
#include <math.h>

#define NN 50000
#define EE 800000
#define F 128
#define BN_EPS 1e-5f
#define SCAN_B 1024
#define NBLK ((NN + SCAN_B - 1) / SCAN_B)

// ---------------- scratch ----------------
__device__ unsigned g_aggh[NN * 192];     // agg features as half2 [n][192]
__device__ unsigned g_Mt[128 * 192];      // M transposed as half2: [o][k/2]
__device__ float4 g_cp[NN * 2];           // {cx,cy,cz,p0},{p1,p2,-,-}
__device__ float g_sum[F];
__device__ float g_sum2[F];
__device__ int   g_cnt[NN];
__device__ int   g_bsum[NBLK];
__device__ int   g_off[NN + 1];
__device__ int   g_cur[NN];
__device__ long long g_pack[EE];          // {w (hi), src*4+order (lo)} CSR order
__device__ float g_ex[EE];                // ex, CSR order

__device__ __forceinline__ unsigned h2u(float a, float b) {
    __half2 h = __floats2half2_rn(a, b);   // low = a
    return *reinterpret_cast<unsigned*>(&h);
}

// ---------------- kernels ----------------
// per-node: proj = attW^T f; pack coords+proj; zero cnt
__global__ void k_proj(const float* __restrict__ feat,
                       const float* __restrict__ coords,
                       const float* __restrict__ attW, int n) {
    int w = (blockIdx.x * blockDim.x + threadIdx.x) >> 5;
    int lane = threadIdx.x & 31;
    if (w >= n) return;
    float4 f = reinterpret_cast<const float4*>(feat + (size_t)w * F)[lane];
    const float4* aw = reinterpret_cast<const float4*>(attW);
    float4 w0 = aw[lane], w1 = aw[32 + lane], w2 = aw[64 + lane];
    float a0 = f.x * w0.x + f.y * w0.y + f.z * w0.z + f.w * w0.w;
    float a1 = f.x * w1.x + f.y * w1.y + f.z * w1.z + f.w * w1.w;
    float a2 = f.x * w2.x + f.y * w2.y + f.z * w2.z + f.w * w2.w;
#pragma unroll
    for (int off = 16; off; off >>= 1) {
        a0 += __shfl_down_sync(0xffffffffu, a0, off);
        a1 += __shfl_down_sync(0xffffffffu, a1, off);
        a2 += __shfl_down_sync(0xffffffffu, a2, off);
    }
    if (lane == 0) {
        float cx = coords[w * 3 + 0], cy = coords[w * 3 + 1], cz = coords[w * 3 + 2];
        g_cp[w * 2 + 0] = make_float4(cx, cy, cz, a0);
        g_cp[w * 2 + 1] = make_float4(a1, a2, 0.f, 0.f);
        g_cnt[w] = 0;
    }
}

// count pass: histogram of dst
__global__ void k_count(const int* __restrict__ dst, int e) {
    int i = blockIdx.x * blockDim.x + threadIdx.x;
    if (i < e) atomicAdd(&g_cnt[dst[i]], 1);
}

// exclusive block scan via warp shuffles
__global__ void k_scan_block(int n) {
    __shared__ int swarp[32];
    int g = blockIdx.x * SCAN_B + threadIdx.x;
    int lane = threadIdx.x & 31;
    int wid = threadIdx.x >> 5;
    int v = (g < n) ? g_cnt[g] : 0;
    int x = v;
#pragma unroll
    for (int off = 1; off < 32; off <<= 1) {
        int t = __shfl_up_sync(0xffffffffu, x, off);
        if (lane >= off) x += t;
    }
    if (lane == 31) swarp[wid] = x;
    __syncthreads();
    if (wid == 0) {
        int y = swarp[lane];
#pragma unroll
        for (int off = 1; off < 32; off <<= 1) {
            int t = __shfl_up_sync(0xffffffffu, y, off);
            if (lane >= off) y += t;
        }
        swarp[lane] = y;
    }
    __syncthreads();
    int prefix = (wid > 0) ? swarp[wid - 1] : 0;
    int incl = x + prefix;
    if (g < n) g_off[g] = incl - v;
    if (threadIdx.x == SCAN_B - 1) g_bsum[blockIdx.x] = incl;
}
__global__ void k_scan_add(int n, int e) {
    __shared__ int sboff;
    if (threadIdx.x == 0) {
        int acc = 0;
        for (int i = 0; i < (int)blockIdx.x; i++) acc += g_bsum[i];
        sboff = acc;
    }
    __syncthreads();
    int g = blockIdx.x * SCAN_B + threadIdx.x;
    if (g < n) {
        int o = g_off[g] + sboff;
        g_off[g] = o;
        g_cur[g] = o;
    }
    if (g == 0) g_off[n] = e;
}

// fused edge compute + direct CSR scatter (single pass over edges)
__global__ void k_edge(const int* __restrict__ src, const int* __restrict__ dst,
                       const int* __restrict__ order, int e) {
    int i = blockIdx.x * blockDim.x + threadIdx.x;
    if (i >= e) return;
    int s = src[i], d = dst[i];
    float4 cs0 = g_cp[s * 2 + 0];
    float4 cs1 = g_cp[s * 2 + 1];
    float4 cd0 = g_cp[d * 2 + 0];
    float dx = cs0.x - cd0.x, dy = cs0.y - cd0.y, dz = cs0.z - cd0.z;
    float a = dx * cs0.w + dy * cs1.x + dz * cs1.y;
    float inv = 1.f / (dx * dx + dy * dy + dz * dz + 1.f);
    float ex = __expf(a);
    float w = ex * inv;
    int pos = atomicAdd(&g_cur[d], 1);
    g_pack[pos] = ((long long)__float_as_int(w) << 32) | (unsigned int)(s * 4 + order[i]);
    g_ex[pos] = ex;
}

// aggregation: warp per dst; smem-staged records; den computed in-warp;
// output stored as half2. No atomics.
__global__ void k_agg(const float* __restrict__ feat, int n) {
    __shared__ long long srec[8][33];
    int wwid = threadIdx.x >> 5;
    int node = (blockIdx.x * blockDim.x + threadIdx.x) >> 5;
    int lane = threadIdx.x & 31;
    if (node >= n) return;
    int beg = g_off[node], end = g_off[node + 1];
    float4 a0 = make_float4(0.f, 0.f, 0.f, 0.f);
    float4 a1 = a0, a2 = a0;
    float densum = 0.f;
    const float4* f4 = reinterpret_cast<const float4*>(feat);
    for (int base = beg; base < end; base += 32) {
        int idx = base + lane;
        if (idx < end) {
            srec[wwid][lane] = g_pack[idx];
            densum += g_ex[idx];
        }
        __syncwarp();
        int cnt = min(32, end - base);
#pragma unroll 4
        for (int j = 0; j < cnt; j++) {
            long long p = srec[wwid][j];
            int id = (int)(unsigned int)p;
            int s = id >> 2, k = id & 3;
            float w = __int_as_float((int)(p >> 32));
            float4 v = f4[(size_t)s * 32 + lane];
            if (k == 0) {
                a0.x += w * v.x; a0.y += w * v.y; a0.z += w * v.z; a0.w += w * v.w;
            } else if (k == 1) {
                a1.x += w * v.x; a1.y += w * v.y; a1.z += w * v.z; a1.w += w * v.w;
            } else {
                a2.x += w * v.x; a2.y += w * v.y; a2.z += w * v.z; a2.w += w * v.w;
            }
        }
        __syncwarp();
    }
#pragma unroll
    for (int off = 16; off; off >>= 1)
        densum += __shfl_down_sync(0xffffffffu, densum, off);
    float den = __shfl_sync(0xffffffffu, densum, 0);
    float invden = 1.f / (den > 0.f ? den : 1.f);
    uint2* gp = reinterpret_cast<uint2*>(g_aggh);
    gp[node * 96 +  0 + lane] = make_uint2(h2u(a0.x * invden, a0.y * invden),
                                           h2u(a0.z * invden, a0.w * invden));
    gp[node * 96 + 32 + lane] = make_uint2(h2u(a1.x * invden, a1.y * invden),
                                           h2u(a1.z * invden, a1.w * invden));
    gp[node * 96 + 64 + lane] = make_uint2(h2u(a2.x * invden, a2.y * invden),
                                           h2u(a2.z * invden, a2.w * invden));
}

// fold: M[r][o] = sum_j linear[r][j]*mlp_w[o][j]; store half TRANSPOSED [o][k/2]
__global__ void k_prep(const float* __restrict__ lin, const float* __restrict__ W) {
    extern __shared__ float smem[];
    float* swT = smem;              // [128][129]
    float* sL = smem + 128 * 129;   // [16][128]
    int t = threadIdx.x;
    int r0 = blockIdx.x * 16;
    if (blockIdx.x == 0) { g_sum[t] = 0.f; g_sum2[t] = 0.f; }
#pragma unroll 4
    for (int j = 0; j < F; j++)
        swT[t * 129 + j] = W[j * F + t];
    for (int idx = t; idx < 16 * F; idx += F)
        sL[idx] = lin[(size_t)r0 * F + idx];
    __syncthreads();
    float acc[16];
#pragma unroll
    for (int r = 0; r < 16; r++) acc[r] = 0.f;
#pragma unroll 4
    for (int j = 0; j < F; j++) {
        float wv = swT[j * 129 + t];
#pragma unroll
        for (int r = 0; r < 16; r++) acc[r] += sL[r * F + j] * wv;
    }
#pragma unroll
    for (int j = 0; j < 8; j++)
        g_Mt[t * 192 + r0 / 2 + j] = h2u(acc[2 * j], acc[2 * j + 1]);
}

// fused output GEMM (fp16 tensor cores m16n8k16, fp32 accum)
// out = relu(Agg[N,384] @ M[384,128] + b); BN partials in registers.
__global__ void __launch_bounds__(256, 1)
k_out_t(const float* __restrict__ mlp_b, float* __restrict__ out, int n) {
    __shared__ unsigned As2[128 * 20];   // [row][kpair], stride 20 (conflict-free)
    __shared__ unsigned Bs2[128 * 20];   // [col][kpair]
    __shared__ float ssum[128], ssum2[128];
    int tid = threadIdx.x;
    int lane = tid & 31;
    int wid = tid >> 5;
    int wm = wid >> 1;
    int wn = wid & 1;
    int row0 = blockIdx.x * 128;

    if (tid < 128) { ssum[tid] = 0.f; ssum2[tid] = 0.f; }

    float c[2][8][4];
#pragma unroll
    for (int i = 0; i < 2; i++)
#pragma unroll
        for (int j = 0; j < 8; j++)
#pragma unroll
            for (int q = 0; q < 4; q++) c[i][j][q] = 0.f;

    // load coords: 2 uint4 per thread for A, 2 for B, per 32-k chunk
    int arow[2], aq[2];
#pragma unroll
    for (int i = 0; i < 2; i++) {
        int lidx = i * 256 + tid;
        arow[i] = lidx >> 2;       // 0..127 (row for A, col for B)
        aq[i] = (lidx & 3) * 4;    // uint offset within 16-kpair span
    }

    uint4 pa[2], pb[2];
#pragma unroll
    for (int i = 0; i < 2; i++) {
        pa[i] = make_uint4(0, 0, 0, 0);
        if (row0 + arow[i] < n)
            pa[i] = *reinterpret_cast<const uint4*>(g_aggh + (size_t)(row0 + arow[i]) * 192 + aq[i]);
        pb[i] = *reinterpret_cast<const uint4*>(g_Mt + (size_t)arow[i] * 192 + aq[i]);
    }

    for (int k0 = 0; k0 < 384; k0 += 32) {
        __syncthreads();
#pragma unroll
        for (int i = 0; i < 2; i++) {
            unsigned* ap = &As2[arow[i] * 20 + aq[i]];
            ap[0] = pa[i].x; ap[1] = pa[i].y; ap[2] = pa[i].z; ap[3] = pa[i].w;
            unsigned* bp = &Bs2[arow[i] * 20 + aq[i]];
            bp[0] = pb[i].x; bp[1] = pb[i].y; bp[2] = pb[i].z; bp[3] = pb[i].w;
        }
        __syncthreads();

        int kn = k0 + 32;
        if (kn < 384) {
            int kb = kn >> 1;
#pragma unroll
            for (int i = 0; i < 2; i++) {
                pa[i] = make_uint4(0, 0, 0, 0);
                if (row0 + arow[i] < n)
                    pa[i] = *reinterpret_cast<const uint4*>(g_aggh + (size_t)(row0 + arow[i]) * 192 + kb + aq[i]);
                pb[i] = *reinterpret_cast<const uint4*>(g_Mt + (size_t)arow[i] * 192 + kb + aq[i]);
            }
        }

#pragma unroll
        for (int kofs = 0; kofs < 16; kofs += 8) {
            unsigned a[2][4];
#pragma unroll
            for (int mt = 0; mt < 2; mt++) {
                int r = wm * 32 + mt * 16 + (lane >> 2);
                int kp = kofs + (lane & 3);
                a[mt][0] = As2[r * 20 + kp];
                a[mt][1] = As2[(r + 8) * 20 + kp];
                a[mt][2] = As2[r * 20 + kp + 4];
                a[mt][3] = As2[(r + 8) * 20 + kp + 4];
            }
#pragma unroll
            for (int nt = 0; nt < 8; nt++) {
                int col = wn * 64 + nt * 8 + (lane >> 2);
                int kp = kofs + (lane & 3);
                unsigned b0 = Bs2[col * 20 + kp];
                unsigned b1 = Bs2[col * 20 + kp + 4];
#pragma unroll
                for (int mt = 0; mt < 2; mt++) {
                    asm volatile(
                        "mma.sync.aligned.m16n8k16.row.col.f32.f16.f16.f32 "
                        "{%0,%1,%2,%3}, {%4,%5,%6,%7}, {%8,%9}, {%0,%1,%2,%3};"
                        : "+f"(c[mt][nt][0]), "+f"(c[mt][nt][1]),
                          "+f"(c[mt][nt][2]), "+f"(c[mt][nt][3])
                        : "r"(a[mt][0]), "r"(a[mt][1]), "r"(a[mt][2]), "r"(a[mt][3]),
                          "r"(b0), "r"(b1));
                }
            }
        }
    }
    __syncthreads();

    float s0[8][2], s2r[8][2];
#pragma unroll
    for (int nt = 0; nt < 8; nt++) {
        s0[nt][0] = 0.f; s0[nt][1] = 0.f;
        s2r[nt][0] = 0.f; s2r[nt][1] = 0.f;
    }
#pragma unroll
    for (int nt = 0; nt < 8; nt++) {
        int colb = wn * 64 + nt * 8 + (lane & 3) * 2;
        float b0 = mlp_b[colb], b1 = mlp_b[colb + 1];
#pragma unroll
        for (int mt = 0; mt < 2; mt++) {
            int rowa = row0 + wm * 32 + mt * 16 + (lane >> 2);
#pragma unroll
            for (int h = 0; h < 2; h++) {
                int row = rowa + h * 8;
                if (row >= n) continue;
                float y0 = c[mt][nt][h * 2 + 0] + b0;
                float y1 = c[mt][nt][h * 2 + 1] + b1;
                y0 = y0 > 0.f ? y0 : 0.f;
                y1 = y1 > 0.f ? y1 : 0.f;
                out[(size_t)row * F + colb] = y0;
                out[(size_t)row * F + colb + 1] = y1;
                s0[nt][0] += y0; s0[nt][1] += y1;
                s2r[nt][0] += y0 * y0; s2r[nt][1] += y1 * y1;
            }
        }
    }
#pragma unroll
    for (int nt = 0; nt < 8; nt++) {
        int colb = wn * 64 + nt * 8 + (lane & 3) * 2;
        atomicAdd(&ssum[colb], s0[nt][0]);
        atomicAdd(&ssum[colb + 1], s0[nt][1]);
        atomicAdd(&ssum2[colb], s2r[nt][0]);
        atomicAdd(&ssum2[colb + 1], s2r[nt][1]);
    }
    __syncthreads();
    if (tid < 128) {
        atomicAdd(&g_sum[tid], ssum[tid]);
        atomicAdd(&g_sum2[tid], ssum2[tid]);
    }
}

__global__ void k_bn(float* __restrict__ out, const float* __restrict__ gamma,
                     const float* __restrict__ beta, int n) {
    int i = blockIdx.x * blockDim.x + threadIdx.x;
    if (i >= n * 32) return;
    int ob = (i & 31) * 4;
    float inv_n = 1.f / (float)n;
    float4 y = reinterpret_cast<float4*>(out)[i];
    float m0 = g_sum[ob + 0] * inv_n, m1 = g_sum[ob + 1] * inv_n;
    float m2 = g_sum[ob + 2] * inv_n, m3 = g_sum[ob + 3] * inv_n;
    float v0 = g_sum2[ob + 0] * inv_n - m0 * m0;
    float v1 = g_sum2[ob + 1] * inv_n - m1 * m1;
    float v2 = g_sum2[ob + 2] * inv_n - m2 * m2;
    float v3 = g_sum2[ob + 3] * inv_n - m3 * m3;
    y.x = (y.x - m0) * rsqrtf(v0 + BN_EPS) * gamma[ob + 0] + beta[ob + 0];
    y.y = (y.y - m1) * rsqrtf(v1 + BN_EPS) * gamma[ob + 1] + beta[ob + 1];
    y.z = (y.z - m2) * rsqrtf(v2 + BN_EPS) * gamma[ob + 2] + beta[ob + 2];
    y.w = (y.w - m3) * rsqrtf(v3 + BN_EPS) * gamma[ob + 3] + beta[ob + 3];
    reinterpret_cast<float4*>(out)[i] = y;
}

// ---------------- launch ----------------
extern "C" void kernel_launch(void* const* d_in, const int* in_sizes, int n_in,
                              void* d_out, int out_size) {
    const float* feature = (const float*)d_in[0];
    const float* coords  = (const float*)d_in[1];
    const int*   src     = (const int*)d_in[2];
    const int*   dst     = (const int*)d_in[3];
    const int*   order   = (const int*)d_in[4];
    const float* linear  = (const float*)d_in[5];
    const float* attW    = (const float*)d_in[6];
    const float* mlp_w   = (const float*)d_in[7];
    const float* mlp_b   = (const float*)d_in[8];
    const float* bn_gamma = (const float*)d_in[9];
    const float* bn_beta  = (const float*)d_in[10];
    float* out = (float*)d_out;

    int n = in_sizes[0] / F;
    int e = in_sizes[2];
    int nb = (n + SCAN_B - 1) / SCAN_B;

    k_proj<<<(n * 32 + 255) / 256, 256>>>(feature, coords, attW, n);

    int smemp = (128 * 129 + 16 * F) * (int)sizeof(float);
    cudaFuncSetAttribute(k_prep, cudaFuncAttributeMaxDynamicSharedMemorySize, smemp);
    k_prep<<<384 / 16, 128, smemp>>>(linear, mlp_w);

    k_count<<<(e + 255) / 256, 256>>>(dst, e);
    k_scan_block<<<nb, SCAN_B>>>(n);
    k_scan_add<<<nb, SCAN_B>>>(n, e);
    k_edge<<<(e + 255) / 256, 256>>>(src, dst, order, e);
    k_agg<<<(n * 32 + 255) / 256, 256>>>(feature, n);

    k_out_t<<<(n + 127) / 128, 256>>>(mlp_b, out, n);
    k_bn<<<(n * 32 + 255) / 256, 256>>>(out, bn_gamma, bn_beta, n);
}